// round 2
// baseline (speedup 1.0000x reference)
#include <cuda_runtime.h>
#include <math_constants.h>

#define EPS 1e-5f
#define BATCH 128
#define HB 64
#define CIN 2048
#define CMID 512
#define HW 196
#define K33 4608   // 512*9

// ---------------- scratch (static device globals; no allocs allowed) --------
__device__ float g_xred[(size_t)BATCH * CMID * HW];   // 51.4 MB
__device__ float g_att [(size_t)BATCH * CMID * CMID]; // 134 MB
__device__ float g_y   [(size_t)BATCH * CMID * HW];   // 51.4 MB
__device__ float g_conv[(size_t)BATCH * CMID * HW];   // 51.4 MB
__device__ float g_z   [BATCH * CMID];
__device__ float g_h   [BATCH * 200];
__device__ float g_scale1[CMID], g_shift1[CMID];
__device__ float g_scale3[CMID], g_shift3[CMID];

// ---------------- K0: fold conv-bias + BN into scale/shift ------------------
__global__ void prep_bn(const float* __restrict__ rb, const float* __restrict__ rg,
                        const float* __restrict__ rbe, const float* __restrict__ rm,
                        const float* __restrict__ rv,
                        const float* __restrict__ cb, const float* __restrict__ cg,
                        const float* __restrict__ cbe, const float* __restrict__ cm,
                        const float* __restrict__ cv) {
    int i = blockIdx.x * blockDim.x + threadIdx.x;
    if (i < CMID) {
        float inv = rg[i] * rsqrtf(rv[i] + EPS);
        g_scale1[i] = inv;
        g_shift1[i] = (rb[i] - rm[i]) * inv + rbe[i];
        float inv3 = cg[i] * rsqrtf(cv[i] + EPS);
        g_scale3[i] = inv3;
        g_shift3[i] = (cb[i] - cm[i]) * inv3 + cbe[i];
    }
}

// ---------------- K1: reduce 1x1 conv GEMM + BN + ReLU ----------------------
// C[b][o][n] = relu(scale1[o] * sum_c W[o,c]*F_b[c,n] + shift1[o])
// 128x128x8 tile, 256 threads, 8x8 microtile
__global__ __launch_bounds__(256) void k_reduce(const float* __restrict__ f2,
                                                const float* __restrict__ f3,
                                                const float* __restrict__ W) {
    int b = blockIdx.z;
    const float* F = (b < HB) ? (f2 + (size_t)b * CIN * HW)
                              : (f3 + (size_t)(b - HB) * CIN * HW);
    int m0 = blockIdx.y * 128;
    int n0 = blockIdx.x * 128;
    int tid = threadIdx.x;
    __shared__ float As[8][132];
    __shared__ float Bs[8][128];
    int arow = tid >> 1,  acol = (tid & 1) * 4;
    int brow = tid >> 5,  bcol = (tid & 31) * 4;
    int tx = tid & 15,    ty = tid >> 4;
    float acc[8][8] = {};
    for (int k0 = 0; k0 < CIN; k0 += 8) {
        float4 av = *(const float4*)(W + (size_t)(m0 + arow) * CIN + k0 + acol);
        As[acol + 0][arow] = av.x; As[acol + 1][arow] = av.y;
        As[acol + 2][arow] = av.z; As[acol + 3][arow] = av.w;
        int n = n0 + bcol;
        float4 bv = make_float4(0.f, 0.f, 0.f, 0.f);
        if (n < HW) bv = *(const float4*)(F + (size_t)(k0 + brow) * HW + n);
        *(float4*)&Bs[brow][bcol] = bv;
        __syncthreads();
        #pragma unroll
        for (int kk = 0; kk < 8; kk++) {
            float ra[8], rb[8];
            #pragma unroll
            for (int i = 0; i < 8; i++) ra[i] = As[kk][ty * 8 + i];
            #pragma unroll
            for (int j = 0; j < 8; j++) rb[j] = Bs[kk][tx * 8 + j];
            #pragma unroll
            for (int i = 0; i < 8; i++)
                #pragma unroll
                for (int j = 0; j < 8; j++)
                    acc[i][j] += ra[i] * rb[j];
        }
        __syncthreads();
    }
    float* out = g_xred + (size_t)b * CMID * HW;
    #pragma unroll
    for (int i = 0; i < 8; i++) {
        int o = m0 + ty * 8 + i;
        float sc = g_scale1[o], sh = g_shift1[o];
        #pragma unroll
        for (int j = 0; j < 8; j++) {
            int n = n0 + tx * 8 + j;
            if (n < HW) out[(size_t)o * HW + n] = fmaxf(acc[i][j] * sc + sh, 0.f);
        }
    }
}

// ---------------- K2: XXt (NT gemm, A=B=xred_b, K=196) ----------------------
__global__ __launch_bounds__(256) void k_xxt() {
    int b = blockIdx.z;
    const float* X = g_xred + (size_t)b * CMID * HW;
    int m0 = blockIdx.y * 128;
    int n0 = blockIdx.x * 128;
    int tid = threadIdx.x;
    __shared__ float As[8][132];
    __shared__ float Bs[8][132];
    int arow = tid >> 1, acol = (tid & 1) * 4;
    int tx = tid & 15,   ty = tid >> 4;
    float acc[8][8] = {};
    for (int k0 = 0; k0 < HW; k0 += 8) {
        float4 av = make_float4(0.f, 0.f, 0.f, 0.f);
        if (k0 + acol < HW)
            av = *(const float4*)(X + (size_t)(m0 + arow) * HW + k0 + acol);
        As[acol + 0][arow] = av.x; As[acol + 1][arow] = av.y;
        As[acol + 2][arow] = av.z; As[acol + 3][arow] = av.w;
        float4 bv = make_float4(0.f, 0.f, 0.f, 0.f);
        if (k0 + acol < HW)
            bv = *(const float4*)(X + (size_t)(n0 + arow) * HW + k0 + acol);
        Bs[acol + 0][arow] = bv.x; Bs[acol + 1][arow] = bv.y;
        Bs[acol + 2][arow] = bv.z; Bs[acol + 3][arow] = bv.w;
        __syncthreads();
        #pragma unroll
        for (int kk = 0; kk < 8; kk++) {
            float ra[8], rb[8];
            #pragma unroll
            for (int i = 0; i < 8; i++) ra[i] = As[kk][ty * 8 + i];
            #pragma unroll
            for (int j = 0; j < 8; j++) rb[j] = Bs[kk][tx * 8 + j];
            #pragma unroll
            for (int i = 0; i < 8; i++)
                #pragma unroll
                for (int j = 0; j < 8; j++)
                    acc[i][j] += ra[i] * rb[j];
        }
        __syncthreads();
    }
    float* out = g_att + (size_t)b * CMID * CMID;
    #pragma unroll
    for (int i = 0; i < 8; i++) {
        int r = m0 + ty * 8 + i;
        #pragma unroll
        for (int j = 0; j < 8; j++)
            out[(size_t)r * CMID + n0 + tx * 8 + j] = acc[i][j];
    }
}

// ---------------- K3: rowwise softmax(-S), in place on g_att ---------------
__global__ __launch_bounds__(256) void k_softmax() {
    int gw = (blockIdx.x * blockDim.x + threadIdx.x) >> 5;
    int lane = threadIdx.x & 31;
    if (gw >= BATCH * CMID) return;
    float* row = g_att + (size_t)gw * CMID;
    float mn = CUDART_INF_F;
    #pragma unroll
    for (int t = 0; t < 16; t++) mn = fminf(mn, row[lane + t * 32]);
    #pragma unroll
    for (int o = 16; o; o >>= 1) mn = fminf(mn, __shfl_xor_sync(~0u, mn, o));
    float e[16], sum = 0.f;
    #pragma unroll
    for (int t = 0; t < 16; t++) { e[t] = __expf(mn - row[lane + t * 32]); sum += e[t]; }
    #pragma unroll
    for (int o = 16; o; o >>= 1) sum += __shfl_xor_sync(~0u, sum, o);
    float inv = 1.f / sum;
    #pragma unroll
    for (int t = 0; t < 16; t++) row[lane + t * 32] = e[t] * inv;
}

// ---------------- K4: y = att @ xred (NN gemm, K=512) -----------------------
__global__ __launch_bounds__(256) void k_ygemm() {
    int b = blockIdx.z;
    const float* A = g_att  + (size_t)b * CMID * CMID;
    const float* B = g_xred + (size_t)b * CMID * HW;
    int m0 = blockIdx.y * 128;
    int n0 = blockIdx.x * 128;
    int tid = threadIdx.x;
    __shared__ float As[8][132];
    __shared__ float Bs[8][128];
    int arow = tid >> 1, acol = (tid & 1) * 4;
    int brow = tid >> 5, bcol = (tid & 31) * 4;
    int tx = tid & 15,   ty = tid >> 4;
    float acc[8][8] = {};
    for (int k0 = 0; k0 < CMID; k0 += 8) {
        float4 av = *(const float4*)(A + (size_t)(m0 + arow) * CMID + k0 + acol);
        As[acol + 0][arow] = av.x; As[acol + 1][arow] = av.y;
        As[acol + 2][arow] = av.z; As[acol + 3][arow] = av.w;
        int n = n0 + bcol;
        float4 bv = make_float4(0.f, 0.f, 0.f, 0.f);
        if (n < HW) bv = *(const float4*)(B + (size_t)(k0 + brow) * HW + n);
        *(float4*)&Bs[brow][bcol] = bv;
        __syncthreads();
        #pragma unroll
        for (int kk = 0; kk < 8; kk++) {
            float ra[8], rb[8];
            #pragma unroll
            for (int i = 0; i < 8; i++) ra[i] = As[kk][ty * 8 + i];
            #pragma unroll
            for (int j = 0; j < 8; j++) rb[j] = Bs[kk][tx * 8 + j];
            #pragma unroll
            for (int i = 0; i < 8; i++)
                #pragma unroll
                for (int j = 0; j < 8; j++)
                    acc[i][j] += ra[i] * rb[j];
        }
        __syncthreads();
    }
    float* out = g_y + (size_t)b * CMID * HW;
    #pragma unroll
    for (int i = 0; i < 8; i++) {
        int o = m0 + ty * 8 + i;
        #pragma unroll
        for (int j = 0; j < 8; j++) {
            int n = n0 + tx * 8 + j;
            if (n < HW) out[(size_t)o * HW + n] = acc[i][j];
        }
    }
}

// ---------------- K5: conv3 3x3 SAME as implicit GEMM + BN + ReLU -----------
__global__ __launch_bounds__(256) void k_conv(const float* __restrict__ W3) {
    int b = blockIdx.z;
    int m0 = blockIdx.y * 128;
    int n0 = blockIdx.x * 128;
    int tid = threadIdx.x;
    __shared__ float As[8][132];
    __shared__ float Bs[8][128];
    int arow = tid >> 1, acol = (tid & 1) * 4;
    int brow = tid >> 5, bcol = (tid & 31) * 4;
    int tx = tid & 15,   ty = tid >> 4;
    const float* yb = g_y + (size_t)b * CMID * HW;
    int ph[4], pw[4]; bool nval[4];
    #pragma unroll
    for (int t = 0; t < 4; t++) {
        int n = n0 + bcol + t;
        nval[t] = (n < HW);
        int p = nval[t] ? n : 0;
        ph[t] = p / 14; pw[t] = p - ph[t] * 14;
    }
    float acc[8][8] = {};
    for (int k0 = 0; k0 < K33; k0 += 8) {
        float4 av = *(const float4*)(W3 + (size_t)(m0 + arow) * K33 + k0 + acol);
        As[acol + 0][arow] = av.x; As[acol + 1][arow] = av.y;
        As[acol + 2][arow] = av.z; As[acol + 3][arow] = av.w;
        int k = k0 + brow;
        int c = k / 9; int rs = k - c * 9; int r = rs / 3; int s = rs - r * 3;
        const float* yc = yb + (size_t)c * HW;
        #pragma unroll
        for (int t = 0; t < 4; t++) {
            float v = 0.f;
            int ih = ph[t] + r - 1, iw = pw[t] + s - 1;
            if (nval[t] && ih >= 0 && ih < 14 && iw >= 0 && iw < 14)
                v = yc[ih * 14 + iw];
            Bs[brow][bcol + t] = v;
        }
        __syncthreads();
        #pragma unroll
        for (int kk = 0; kk < 8; kk++) {
            float ra[8], rb[8];
            #pragma unroll
            for (int i = 0; i < 8; i++) ra[i] = As[kk][ty * 8 + i];
            #pragma unroll
            for (int j = 0; j < 8; j++) rb[j] = Bs[kk][tx * 8 + j];
            #pragma unroll
            for (int i = 0; i < 8; i++)
                #pragma unroll
                for (int j = 0; j < 8; j++)
                    acc[i][j] += ra[i] * rb[j];
        }
        __syncthreads();
    }
    float* out = g_conv + (size_t)b * CMID * HW;
    #pragma unroll
    for (int i = 0; i < 8; i++) {
        int o = m0 + ty * 8 + i;
        float sc = g_scale3[o], sh = g_shift3[o];
        #pragma unroll
        for (int j = 0; j < 8; j++) {
            int n = n0 + tx * 8 + j;
            if (n < HW) out[(size_t)o * HW + n] = fmaxf(acc[i][j] * sc + sh, 0.f);
        }
    }
}

// ---------------- K6: global average pool -> g_z ----------------------------
__global__ __launch_bounds__(256) void k_mean() {
    int gw = (blockIdx.x * blockDim.x + threadIdx.x) >> 5;
    int lane = threadIdx.x & 31;
    if (gw >= BATCH * CMID) return;
    const float* row = g_conv + (size_t)gw * HW;
    float sum = 0.f;
    for (int j = lane; j < HW; j += 32) sum += row[j];
    #pragma unroll
    for (int o = 16; o; o >>= 1) sum += __shfl_xor_sync(~0u, sum, o);
    if (lane == 0) g_z[gw] = sum * (1.f / HW);
}

// ---------------- K7: fc1 + ReLU (warp per output) --------------------------
__global__ __launch_bounds__(256) void k_fc1(const float* __restrict__ w,
                                             const float* __restrict__ bias) {
    int gw = (blockIdx.x * blockDim.x + threadIdx.x) >> 5;
    int lane = threadIdx.x & 31;
    if (gw >= BATCH * 200) return;
    int b = gw / 200, j = gw - b * 200;
    const float* zr = g_z + b * CMID;
    const float* wr = w + (size_t)j * CMID;
    float s = 0.f;
    for (int k = lane; k < CMID; k += 32) s += zr[k] * wr[k];
    #pragma unroll
    for (int o = 16; o; o >>= 1) s += __shfl_xor_sync(~0u, s, o);
    if (lane == 0) g_h[gw] = fmaxf(s + bias[j], 0.f);
}

// ---------------- K8: fc2 + branch-sum epilogue -----------------------------
__global__ __launch_bounds__(256) void k_fc2(const float* __restrict__ w,
                                             const float* __restrict__ bias,
                                             float* __restrict__ out) {
    int gw = (blockIdx.x * blockDim.x + threadIdx.x) >> 5;
    int lane = threadIdx.x & 31;
    if (gw >= HB * 200) return;
    int b = gw / 200, j = gw - b * 200;
    const float* h1 = g_h + (size_t)b * 200;
    const float* h2 = g_h + (size_t)(b + HB) * 200;
    const float* wr = w + (size_t)j * 200;
    float s = 0.f;
    for (int k = lane; k < 200; k += 32) s += (h1[k] + h2[k]) * wr[k];
    #pragma unroll
    for (int o = 16; o; o >>= 1) s += __shfl_xor_sync(~0u, s, o);
    if (lane == 0) out[gw] = s + 2.f * bias[j];
}

// ---------------- launch ----------------------------------------------------
extern "C" void kernel_launch(void* const* d_in, const int* in_sizes, int n_in,
                              void* d_out, int out_size) {
    const float* f2  = (const float*)d_in[0];
    const float* f3  = (const float*)d_in[1];
    const float* rw  = (const float*)d_in[2];
    const float* rb  = (const float*)d_in[3];
    const float* rg  = (const float*)d_in[4];
    const float* rbe = (const float*)d_in[5];
    const float* rm  = (const float*)d_in[6];
    const float* rv  = (const float*)d_in[7];
    const float* c3w = (const float*)d_in[8];
    const float* c3b = (const float*)d_in[9];
    const float* c3g = (const float*)d_in[10];
    const float* c3be= (const float*)d_in[11];
    const float* c3m = (const float*)d_in[12];
    const float* c3v = (const float*)d_in[13];
    const float* f1w = (const float*)d_in[14];
    const float* f1b = (const float*)d_in[15];
    const float* f2w = (const float*)d_in[16];
    const float* f2b = (const float*)d_in[17];
    float* out = (float*)d_out;

    prep_bn<<<2, 256>>>(rb, rg, rbe, rm, rv, c3b, c3g, c3be, c3m, c3v);
    k_reduce<<<dim3(2, 4, BATCH), 256>>>(f2, f3, rw);
    k_xxt<<<dim3(4, 4, BATCH), 256>>>();
    k_softmax<<<(BATCH * CMID) / 8, 256>>>();
    k_ygemm<<<dim3(2, 4, BATCH), 256>>>();
    k_conv<<<dim3(2, 4, BATCH), 256>>>(c3w);
    k_mean<<<(BATCH * CMID) / 8, 256>>>();
    k_fc1<<<(BATCH * 200 + 7) / 8, 256>>>(f1w, f1b);
    k_fc2<<<(HB * 200 + 7) / 8, 256>>>(f2w, f2b, out);
}

// round 3
// speedup vs baseline: 1.5609x; 1.5609x over previous
#include <cuda_runtime.h>
#include <math_constants.h>

#define EPS 1e-5f
#define BATCH 128
#define HB 64
#define CIN 2048
#define CMID 512
#define HW 196
#define K33 4608   // 512*9
#define NFLAT (BATCH * HW)   // 25088 = 196 * 128 exact

// ---------------- scratch (static device globals; no allocs allowed) --------
__device__ float g_xred[(size_t)BATCH * CMID * HW];   // 51.4 MB
__device__ float g_att [(size_t)BATCH * CMID * CMID]; // 134 MB
__device__ float g_y   [(size_t)BATCH * CMID * HW];   // 51.4 MB
__device__ float g_conv[(size_t)BATCH * CMID * HW];   // 51.4 MB
__device__ float g_z   [BATCH * CMID];
__device__ float g_h   [BATCH * 200];
__device__ float g_scale1[CMID], g_shift1[CMID];
__device__ float g_scale3[CMID], g_shift3[CMID];

// ---------------- packed fp32x2 FMA helpers ---------------------------------
__device__ __forceinline__ void ffma2(unsigned long long& d,
                                      unsigned long long a,
                                      unsigned long long b) {
    asm("fma.rn.f32x2 %0, %1, %2, %0;" : "+l"(d) : "l"(a), "l"(b));
}
__device__ __forceinline__ unsigned long long dup2(float a) {
    unsigned long long r;
    unsigned int u = __float_as_uint(a);
    asm("mov.b64 %0, {%1, %1};" : "=l"(r) : "r"(u));
    return r;
}

// micro-kernel: 8 rows (contiguous, aoff=ty*8) x 8 cols (4 pairs at
// boff=tx*2, pair stride 32) over 8 k-steps. B reads are LDS.64 at word
// stride 2 -> conflict-free across the 16 tx values.
template<int BWA, int BWB>
__device__ __forceinline__ void micro_step(const float* As, const float* Bs,
                                           int aoff, int boff,
                                           unsigned long long acc[8][4]) {
    #pragma unroll
    for (int kk = 0; kk < 8; kk++) {
        unsigned long long ra2[8], rb2[4];
        #pragma unroll
        for (int i = 0; i < 8; i++) ra2[i] = dup2(As[kk * BWA + aoff + i]);
        #pragma unroll
        for (int s = 0; s < 4; s++)
            rb2[s] = *(const unsigned long long*)(Bs + kk * BWB + boff + 32 * s);
        #pragma unroll
        for (int i = 0; i < 8; i++)
            #pragma unroll
            for (int s = 0; s < 4; s++)
                ffma2(acc[i][s], ra2[i], rb2[s]);
    }
}

// ---------------- K0: fold conv-bias + BN into scale/shift ------------------
__global__ void prep_bn(const float* __restrict__ rb, const float* __restrict__ rg,
                        const float* __restrict__ rbe, const float* __restrict__ rm,
                        const float* __restrict__ rv,
                        const float* __restrict__ cb, const float* __restrict__ cg,
                        const float* __restrict__ cbe, const float* __restrict__ cm,
                        const float* __restrict__ cv) {
    int i = blockIdx.x * blockDim.x + threadIdx.x;
    if (i < CMID) {
        float inv = rg[i] * rsqrtf(rv[i] + EPS);
        g_scale1[i] = inv;
        g_shift1[i] = (rb[i] - rm[i]) * inv + rbe[i];
        float inv3 = cg[i] * rsqrtf(cv[i] + EPS);
        g_scale3[i] = inv3;
        g_shift3[i] = (cb[i] - cm[i]) * inv3 + cbe[i];
    }
}

// ---------------- K1: reduce 1x1 conv GEMM + BN + ReLU ----------------------
// N flattened over (batch, hw): 25088 cols = 196 exact tiles of 128.
__global__ __launch_bounds__(256) void k_reduce(const float* __restrict__ f2,
                                                const float* __restrict__ f3,
                                                const float* __restrict__ W) {
    int n0 = blockIdx.x * 128;
    int m0 = blockIdx.y * 128;
    int tid = threadIdx.x;
    __shared__ float As[8 * 132];
    __shared__ float Bs[8 * 128];
    int arow = tid >> 1, acol = (tid & 1) * 4;
    int brow = tid >> 5, bcol = (tid & 31) * 4;
    int tx = tid & 15,   ty = tid >> 4;

    const float* bptr[4];
    #pragma unroll
    for (int t = 0; t < 4; t++) {
        int col = n0 + bcol + t;
        int b = col / HW, n = col - b * HW;
        const float* F = (b < HB) ? f2 + (size_t)b * CIN * HW
                                  : f3 + (size_t)(b - HB) * CIN * HW;
        bptr[t] = F + (size_t)brow * HW + n;
    }
    const float* wp = W + (size_t)(m0 + arow) * CIN + acol;

    unsigned long long acc[8][4] = {};
    for (int k0 = 0; k0 < CIN; k0 += 8) {
        float4 av = *(const float4*)(wp + k0);
        As[(acol + 0) * 132 + arow] = av.x;
        As[(acol + 1) * 132 + arow] = av.y;
        As[(acol + 2) * 132 + arow] = av.z;
        As[(acol + 3) * 132 + arow] = av.w;
        float4 bv;
        bv.x = bptr[0][(size_t)k0 * HW];
        bv.y = bptr[1][(size_t)k0 * HW];
        bv.z = bptr[2][(size_t)k0 * HW];
        bv.w = bptr[3][(size_t)k0 * HW];
        *(float4*)&Bs[brow * 128 + bcol] = bv;
        __syncthreads();
        micro_step<132, 128>(As, Bs, ty * 8, tx * 2, acc);
        __syncthreads();
    }
    #pragma unroll
    for (int i = 0; i < 8; i++) {
        int o = m0 + ty * 8 + i;
        float sc = g_scale1[o], sh = g_shift1[o];
        #pragma unroll
        for (int s = 0; s < 4; s++) {
            union { unsigned long long u; float2 f; } v; v.u = acc[i][s];
            int c0 = n0 + s * 32 + tx * 2;
            int b0 = c0 / HW, e0 = c0 - b0 * HW;
            g_xred[((size_t)b0 * CMID + o) * HW + e0] = fmaxf(v.f.x * sc + sh, 0.f);
            int c1 = c0 + 1;
            int b1 = c1 / HW, e1 = c1 - b1 * HW;
            g_xred[((size_t)b1 * CMID + o) * HW + e1] = fmaxf(v.f.y * sc + sh, 0.f);
        }
    }
}

// ---------------- K2: XXt (NT gemm, A=B=xred_b, K=196) ----------------------
__global__ __launch_bounds__(256) void k_xxt() {
    int b = blockIdx.z;
    const float* X = g_xred + (size_t)b * CMID * HW;
    int m0 = blockIdx.y * 128;
    int n0 = blockIdx.x * 128;
    int tid = threadIdx.x;
    __shared__ float As[8 * 132];
    __shared__ float Bs[8 * 132];
    int arow = tid >> 1, acol = (tid & 1) * 4;
    int tx = tid & 15,   ty = tid >> 4;
    unsigned long long acc[8][4] = {};
    for (int k0 = 0; k0 < HW; k0 += 8) {
        float4 av = make_float4(0.f, 0.f, 0.f, 0.f);
        float4 bv = make_float4(0.f, 0.f, 0.f, 0.f);
        if (k0 + acol < HW) {
            av = *(const float4*)(X + (size_t)(m0 + arow) * HW + k0 + acol);
            bv = *(const float4*)(X + (size_t)(n0 + arow) * HW + k0 + acol);
        }
        As[(acol + 0) * 132 + arow] = av.x;
        As[(acol + 1) * 132 + arow] = av.y;
        As[(acol + 2) * 132 + arow] = av.z;
        As[(acol + 3) * 132 + arow] = av.w;
        Bs[(acol + 0) * 132 + arow] = bv.x;
        Bs[(acol + 1) * 132 + arow] = bv.y;
        Bs[(acol + 2) * 132 + arow] = bv.z;
        Bs[(acol + 3) * 132 + arow] = bv.w;
        __syncthreads();
        micro_step<132, 132>(As, Bs, ty * 8, tx * 2, acc);
        __syncthreads();
    }
    float* out = g_att + (size_t)b * CMID * CMID;
    #pragma unroll
    for (int i = 0; i < 8; i++) {
        int r = m0 + ty * 8 + i;
        #pragma unroll
        for (int s = 0; s < 4; s++) {
            union { unsigned long long u; float2 f; } v; v.u = acc[i][s];
            int c = n0 + s * 32 + tx * 2;
            out[(size_t)r * CMID + c]     = v.f.x;
            out[(size_t)r * CMID + c + 1] = v.f.y;
        }
    }
}

// ---------------- K3: rowwise softmax(-S), in place on g_att ---------------
__global__ __launch_bounds__(256) void k_softmax() {
    int gw = (blockIdx.x * blockDim.x + threadIdx.x) >> 5;
    int lane = threadIdx.x & 31;
    if (gw >= BATCH * CMID) return;
    float* row = g_att + (size_t)gw * CMID;
    float mn = CUDART_INF_F;
    #pragma unroll
    for (int t = 0; t < 16; t++) mn = fminf(mn, row[lane + t * 32]);
    #pragma unroll
    for (int o = 16; o; o >>= 1) mn = fminf(mn, __shfl_xor_sync(~0u, mn, o));
    float e[16], sum = 0.f;
    #pragma unroll
    for (int t = 0; t < 16; t++) { e[t] = __expf(mn - row[lane + t * 32]); sum += e[t]; }
    #pragma unroll
    for (int o = 16; o; o >>= 1) sum += __shfl_xor_sync(~0u, sum, o);
    float inv = 1.f / sum;
    #pragma unroll
    for (int t = 0; t < 16; t++) row[lane + t * 32] = e[t] * inv;
}

// ---------------- K4: y = att @ xred (NN gemm, K=512) -----------------------
__global__ __launch_bounds__(256) void k_ygemm() {
    int b = blockIdx.z;
    const float* A = g_att  + (size_t)b * CMID * CMID;
    const float* B = g_xred + (size_t)b * CMID * HW;
    int m0 = blockIdx.y * 128;
    int n0 = blockIdx.x * 128;
    int tid = threadIdx.x;
    __shared__ float As[8 * 132];
    __shared__ float Bs[8 * 128];
    int arow = tid >> 1, acol = (tid & 1) * 4;
    int brow = tid >> 5, bcol = (tid & 31) * 4;
    int tx = tid & 15,   ty = tid >> 4;
    unsigned long long acc[8][4] = {};
    for (int k0 = 0; k0 < CMID; k0 += 8) {
        float4 av = *(const float4*)(A + (size_t)(m0 + arow) * CMID + k0 + acol);
        As[(acol + 0) * 132 + arow] = av.x;
        As[(acol + 1) * 132 + arow] = av.y;
        As[(acol + 2) * 132 + arow] = av.z;
        As[(acol + 3) * 132 + arow] = av.w;
        int n = n0 + bcol;
        float4 bv = make_float4(0.f, 0.f, 0.f, 0.f);
        if (n < HW) bv = *(const float4*)(B + (size_t)(k0 + brow) * HW + n);
        *(float4*)&Bs[brow * 128 + bcol] = bv;
        __syncthreads();
        micro_step<132, 128>(As, Bs, ty * 8, tx * 2, acc);
        __syncthreads();
    }
    float* out = g_y + (size_t)b * CMID * HW;
    #pragma unroll
    for (int i = 0; i < 8; i++) {
        int o = m0 + ty * 8 + i;
        #pragma unroll
        for (int s = 0; s < 4; s++) {
            union { unsigned long long u; float2 f; } v; v.u = acc[i][s];
            int c = n0 + s * 32 + tx * 2;
            if (c < HW)     out[(size_t)o * HW + c]     = v.f.x;
            if (c + 1 < HW) out[(size_t)o * HW + c + 1] = v.f.y;
        }
    }
}

// ---------------- K5: conv3 3x3 SAME implicit GEMM + BN + ReLU --------------
// N flattened over (batch, hw): 196 exact tiles of 128 (weights shared).
__global__ __launch_bounds__(256) void k_conv(const float* __restrict__ W3) {
    int n0 = blockIdx.x * 128;
    int m0 = blockIdx.y * 128;
    int tid = threadIdx.x;
    __shared__ float As[8 * 132];
    __shared__ float Bs[8 * 128];
    int arow = tid >> 1, acol = (tid & 1) * 4;
    int brow = tid >> 5, bcol = (tid & 31) * 4;
    int tx = tid & 15,   ty = tid >> 4;

    const float* ybase[4];
    int ph[4], pw[4];
    #pragma unroll
    for (int t = 0; t < 4; t++) {
        int col = n0 + bcol + t;
        int b = col / HW, p = col - b * HW;
        ph[t] = p / 14; pw[t] = p - ph[t] * 14;
        ybase[t] = g_y + (size_t)b * CMID * HW;
    }
    const float* wp = W3 + (size_t)(m0 + arow) * K33 + acol;

    unsigned long long acc[8][4] = {};
    for (int k0 = 0; k0 < K33; k0 += 8) {
        float4 av = *(const float4*)(wp + k0);
        As[(acol + 0) * 132 + arow] = av.x;
        As[(acol + 1) * 132 + arow] = av.y;
        As[(acol + 2) * 132 + arow] = av.z;
        As[(acol + 3) * 132 + arow] = av.w;
        int k = k0 + brow;
        int c = k / 9; int rs = k - c * 9; int r = rs / 3; int s2 = rs - r * 3;
        float4 bv;
        float vv[4];
        #pragma unroll
        for (int t = 0; t < 4; t++) {
            int ih = ph[t] + r - 1, iw = pw[t] + s2 - 1;
            vv[t] = ((unsigned)ih < 14u && (unsigned)iw < 14u)
                  ? ybase[t][(size_t)c * HW + ih * 14 + iw] : 0.f;
        }
        bv.x = vv[0]; bv.y = vv[1]; bv.z = vv[2]; bv.w = vv[3];
        *(float4*)&Bs[brow * 128 + bcol] = bv;
        __syncthreads();
        micro_step<132, 128>(As, Bs, ty * 8, tx * 2, acc);
        __syncthreads();
    }
    #pragma unroll
    for (int i = 0; i < 8; i++) {
        int o = m0 + ty * 8 + i;
        float sc = g_scale3[o], sh = g_shift3[o];
        #pragma unroll
        for (int s = 0; s < 4; s++) {
            union { unsigned long long u; float2 f; } v; v.u = acc[i][s];
            int c0 = n0 + s * 32 + tx * 2;
            int b0 = c0 / HW, e0 = c0 - b0 * HW;
            g_conv[((size_t)b0 * CMID + o) * HW + e0] = fmaxf(v.f.x * sc + sh, 0.f);
            int c1 = c0 + 1;
            int b1 = c1 / HW, e1 = c1 - b1 * HW;
            g_conv[((size_t)b1 * CMID + o) * HW + e1] = fmaxf(v.f.y * sc + sh, 0.f);
        }
    }
}

// ---------------- K6: global average pool -> g_z ----------------------------
__global__ __launch_bounds__(256) void k_mean() {
    int gw = (blockIdx.x * blockDim.x + threadIdx.x) >> 5;
    int lane = threadIdx.x & 31;
    if (gw >= BATCH * CMID) return;
    const float* row = g_conv + (size_t)gw * HW;
    float sum = 0.f;
    for (int j = lane; j < HW; j += 32) sum += row[j];
    #pragma unroll
    for (int o = 16; o; o >>= 1) sum += __shfl_xor_sync(~0u, sum, o);
    if (lane == 0) g_z[gw] = sum * (1.f / HW);
}

// ---------------- K7: fc1 + ReLU (warp per output) --------------------------
__global__ __launch_bounds__(256) void k_fc1(const float* __restrict__ w,
                                             const float* __restrict__ bias) {
    int gw = (blockIdx.x * blockDim.x + threadIdx.x) >> 5;
    int lane = threadIdx.x & 31;
    if (gw >= BATCH * 200) return;
    int b = gw / 200, j = gw - b * 200;
    const float* zr = g_z + b * CMID;
    const float* wr = w + (size_t)j * CMID;
    float s = 0.f;
    for (int k = lane; k < CMID; k += 32) s += zr[k] * wr[k];
    #pragma unroll
    for (int o = 16; o; o >>= 1) s += __shfl_xor_sync(~0u, s, o);
    if (lane == 0) g_h[gw] = fmaxf(s + bias[j], 0.f);
}

// ---------------- K8: fc2 + branch-sum epilogue -----------------------------
__global__ __launch_bounds__(256) void k_fc2(const float* __restrict__ w,
                                             const float* __restrict__ bias,
                                             float* __restrict__ out) {
    int gw = (blockIdx.x * blockDim.x + threadIdx.x) >> 5;
    int lane = threadIdx.x & 31;
    if (gw >= HB * 200) return;
    int b = gw / 200, j = gw - b * 200;
    const float* h1 = g_h + (size_t)b * 200;
    const float* h2 = g_h + (size_t)(b + HB) * 200;
    const float* wr = w + (size_t)j * 200;
    float s = 0.f;
    for (int k = lane; k < 200; k += 32) s += (h1[k] + h2[k]) * wr[k];
    #pragma unroll
    for (int o = 16; o; o >>= 1) s += __shfl_xor_sync(~0u, s, o);
    if (lane == 0) out[gw] = s + 2.f * bias[j];
}

// ---------------- launch ----------------------------------------------------
extern "C" void kernel_launch(void* const* d_in, const int* in_sizes, int n_in,
                              void* d_out, int out_size) {
    const float* f2  = (const float*)d_in[0];
    const float* f3  = (const float*)d_in[1];
    const float* rw  = (const float*)d_in[2];
    const float* rb  = (const float*)d_in[3];
    const float* rg  = (const float*)d_in[4];
    const float* rbe = (const float*)d_in[5];
    const float* rm  = (const float*)d_in[6];
    const float* rv  = (const float*)d_in[7];
    const float* c3w = (const float*)d_in[8];
    const float* c3b = (const float*)d_in[9];
    const float* c3g = (const float*)d_in[10];
    const float* c3be= (const float*)d_in[11];
    const float* c3m = (const float*)d_in[12];
    const float* c3v = (const float*)d_in[13];
    const float* f1w = (const float*)d_in[14];
    const float* f1b = (const float*)d_in[15];
    const float* f2w = (const float*)d_in[16];
    const float* f2b = (const float*)d_in[17];
    float* out = (float*)d_out;

    prep_bn<<<2, 256>>>(rb, rg, rbe, rm, rv, c3b, c3g, c3be, c3m, c3v);
    k_reduce<<<dim3(NFLAT / 128, 4), 256>>>(f2, f3, rw);
    k_xxt<<<dim3(4, 4, BATCH), 256>>>();
    k_softmax<<<(BATCH * CMID) / 8, 256>>>();
    k_ygemm<<<dim3(2, 4, BATCH), 256>>>();
    k_conv<<<dim3(NFLAT / 128, 4), 256>>>(c3w);
    k_mean<<<(BATCH * CMID) / 8, 256>>>();
    k_fc1<<<(BATCH * 200 + 7) / 8, 256>>>(f1w, f1b);
    k_fc2<<<(HB * 200 + 7) / 8, 256>>>(f2w, f2b, out);
}

// round 6
// speedup vs baseline: 3.6995x; 2.3701x over previous
#include <cuda_runtime.h>
#include <cuda_bf16.h>
#include <cstdint>
#include <math_constants.h>

#define EPS 1e-5f
#define HB 64
#define BATCH 128
#define CIN 2048
#define CMID 512
#define HW 196
#define HWP 256
#define K33 4608
#define NFLAT 25088   // 128*196 = 196 tiles of 128 exactly

// ---------------- scratch (static device globals; zero-init at load) --------
__device__ __nv_bfloat16 g_fT_h[(size_t)NFLAT * CIN];
__device__ __nv_bfloat16 g_fT_l[(size_t)NFLAT * CIN];
__device__ __nv_bfloat16 g_x_h [(size_t)BATCH * CMID * HWP];  // pad cols stay 0
__device__ __nv_bfloat16 g_x_l [(size_t)BATCH * CMID * HWP];
__device__ __nv_bfloat16 g_xT_h[(size_t)BATCH * HW * CMID];
__device__ __nv_bfloat16 g_xT_l[(size_t)BATCH * HW * CMID];
__device__ float         g_att [(size_t)BATCH * CMID * CMID];
__device__ __nv_bfloat16 g_att_h[(size_t)BATCH * CMID * CMID];
__device__ __nv_bfloat16 g_att_l[(size_t)BATCH * CMID * CMID];
__device__ __nv_bfloat16 g_yT_h[(size_t)BATCH * HW * CMID];
__device__ __nv_bfloat16 g_yT_l[(size_t)BATCH * HW * CMID];
__device__ __nv_bfloat16 g_w1_h[(size_t)CMID * CIN];
__device__ __nv_bfloat16 g_w1_l[(size_t)CMID * CIN];
__device__ __nv_bfloat16 g_w3_h[(size_t)CMID * K33];   // reordered k = rs*512 + c
__device__ __nv_bfloat16 g_w3_l[(size_t)CMID * K33];
__device__ float g_zsum[BATCH * CMID];
__device__ float g_h[BATCH * 200];
__device__ float g_scale1[CMID], g_shift1[CMID], g_scale3[CMID], g_shift3[CMID];

// ---------------- ptx helpers (all non-'a' gated: sm_80-level) --------------
__device__ __forceinline__ uint32_t smem_u32(const void* p) {
    uint32_t a;
    asm("{ .reg .u64 t; cvta.to.shared.u64 t, %1; cvt.u32.u64 %0, t; }"
        : "=r"(a) : "l"(p));
    return a;
}
__device__ __forceinline__ void cp16(uint32_t dst, const void* src) {
    asm volatile("cp.async.ca.shared.global [%0], [%1], 16;"
                 :: "r"(dst), "l"(src));
}
__device__ __forceinline__ void cp16z(uint32_t dst, const void* src, int ok) {
    int sz = ok ? 16 : 0;
    asm volatile("cp.async.ca.shared.global [%0], [%1], 16, %2;"
                 :: "r"(dst), "l"(src), "r"(sz));
}
__device__ __forceinline__ void cp_commit() {
    asm volatile("cp.async.commit_group;" ::: "memory");
}
template<int N> __device__ __forceinline__ void cp_wait() {
    asm volatile("cp.async.wait_group %0;" :: "n"(N) : "memory");
}
__device__ __forceinline__ void ldm4(uint32_t* r, uint32_t addr) {
    asm volatile("ldmatrix.sync.aligned.m8n8.x4.shared.b16 {%0,%1,%2,%3}, [%4];"
                 : "=r"(r[0]), "=r"(r[1]), "=r"(r[2]), "=r"(r[3]) : "r"(addr));
}
__device__ __forceinline__ void ldm2(uint32_t* r, uint32_t addr) {
    asm volatile("ldmatrix.sync.aligned.m8n8.x2.shared.b16 {%0,%1}, [%2];"
                 : "=r"(r[0]), "=r"(r[1]) : "r"(addr));
}
__device__ __forceinline__ void mma16816(float* c, const uint32_t* a,
                                         const uint32_t* b) {
    asm volatile(
        "mma.sync.aligned.m16n8k16.row.col.f32.bf16.bf16.f32 "
        "{%0,%1,%2,%3}, {%4,%5,%6,%7}, {%8,%9}, {%0,%1,%2,%3};"
        : "+f"(c[0]), "+f"(c[1]), "+f"(c[2]), "+f"(c[3])
        : "r"(a[0]), "r"(a[1]), "r"(a[2]), "r"(a[3]), "r"(b[0]), "r"(b[1]));
}
__device__ __forceinline__ void split_bf16(float v, __nv_bfloat16& hi,
                                           __nv_bfloat16& lo) {
    hi = __float2bfloat16(v);
    lo = __float2bfloat16(v - __bfloat162float(hi));
}

// ---------------- SMEM geometry ---------------------------------------------
// tile = 128 rows x 32 bf16 cols, padded row stride 40 bf16 (80 B) -> the 8
// ldmatrix row addresses cover all 32 banks (20 words/row, gcd-free).
#define TROW 80
#define TILE_B (128 * TROW)          // 10240 B
#define STAGE_B (4 * TILE_B)         // Ah, Al, Bh, Bl = 40960 B
#define DYN_SMEM (2 * STAGE_B)       // double buffered = 81920 B

// contiguous 128x32 tile load via cp.async: 512 16B chunks / 256 threads
__device__ __forceinline__ void cpa_tile(uint32_t sdst, const __nv_bfloat16* g,
                                         size_t stride, int k0, int tid) {
    #pragma unroll
    for (int it = 0; it < 2; it++) {
        int ch = it * 256 + tid;
        int row = ch >> 2, seg = ch & 3;
        cp16(sdst + row * TROW + seg * 16,
             g + (size_t)row * stride + k0 + seg * 8);
    }
}
__device__ __forceinline__ void cpa_tile_clamp(uint32_t sdst,
                                               const __nv_bfloat16* g,
                                               size_t stride, int row0,
                                               int maxrow, int k0, int tid) {
    #pragma unroll
    for (int it = 0; it < 2; it++) {
        int ch = it * 256 + tid;
        int row = ch >> 2, seg = ch & 3;
        int rg = row0 + row; if (rg > maxrow) rg = maxrow;
        cp16(sdst + row * TROW + seg * 16,
             g + (size_t)rg * stride + k0 + seg * 8);
    }
}

// one k16 slab: 4 m-atoms x 4 n-atoms of m16n8k16
__device__ __forceinline__ void mma_k16(uint32_t aBase, uint32_t bBase, int kk,
                                        int lane, float c[4][4][4]) {
    uint32_t a[4][4], b[4][2];
    int arow = lane & 15, asel = lane >> 4;
    #pragma unroll
    for (int am = 0; am < 4; am++)
        ldm4(a[am], aBase + (am * 16 + arow) * TROW + (kk + asel * 8) * 2);
    int brow = lane & 7, bsel = (lane >> 3) & 1;
    #pragma unroll
    for (int bn = 0; bn < 4; bn++)
        ldm2(b[bn], bBase + (bn * 8 + brow) * TROW + (kk + bsel * 8) * 2);
    #pragma unroll
    for (int am = 0; am < 4; am++)
        #pragma unroll
        for (int bn = 0; bn < 4; bn++)
            mma16816(c[am][bn], a[am], b[bn]);
}

// full stage compute: pairs (Ah,Bh), (Ah,Bl), (Al,Bh) over kk = 0, 16
__device__ __forceinline__ void stage_compute(uint32_t sb, int wm, int wn,
                                              int lane, float c[4][4][4]) {
    uint32_t Ah = sb + wm * TROW,            Al = Ah + TILE_B;
    uint32_t Bh = sb + 2 * TILE_B + wn * TROW, Bl = Bh + TILE_B;
    #pragma unroll
    for (int kk = 0; kk < 32; kk += 16) {
        mma_k16(Ah, Bh, kk, lane, c);
        mma_k16(Ah, Bl, kk, lane, c);
        mma_k16(Al, Bh, kk, lane, c);
    }
}

#define GEMM_VARS()                                                            \
    extern __shared__ __align__(16) char dsm[];                                \
    uint32_t sb0 = smem_u32(dsm);                                              \
    int tid = threadIdx.x, wid = tid >> 5, lane = tid & 31;                    \
    int wm = (wid >> 2) * 64, wn = (wid & 3) * 32;                             \
    float c[4][4][4] = {};

// ---------------- small prep kernels ----------------------------------------
__global__ void k_zero() {
    g_zsum[blockIdx.x * blockDim.x + threadIdx.x] = 0.f;
}
__global__ void prep_bn(const float* __restrict__ rb, const float* __restrict__ rg,
                        const float* __restrict__ rbe, const float* __restrict__ rm,
                        const float* __restrict__ rv,
                        const float* __restrict__ cb, const float* __restrict__ cg,
                        const float* __restrict__ cbe, const float* __restrict__ cm,
                        const float* __restrict__ cv) {
    int i = blockIdx.x * blockDim.x + threadIdx.x;
    if (i < CMID) {
        float inv = rg[i] * rsqrtf(rv[i] + EPS);
        g_scale1[i] = inv;
        g_shift1[i] = (rb[i] - rm[i]) * inv + rbe[i];
        float inv3 = cg[i] * rsqrtf(cv[i] + EPS);
        g_scale3[i] = inv3;
        g_shift3[i] = (cb[i] - cm[i]) * inv3 + cbe[i];
    }
}
__global__ void cvt_w1(const float* __restrict__ w) {
    int i = blockIdx.x * blockDim.x + threadIdx.x;
    __nv_bfloat16 hi, lo; split_bf16(w[i], hi, lo);
    g_w1_h[i] = hi; g_w1_l[i] = lo;
}
__global__ void cvt_w3(const float* __restrict__ w) {
    int i = blockIdx.x * blockDim.x + threadIdx.x;   // over 512*4608
    int o = i / K33, k = i - o * K33;
    int rs = k >> 9, cc = k & 511;
    int r = rs / 3, s = rs - r * 3;
    float v = w[((o * CMID + cc) * 3 + r) * 3 + s];
    __nv_bfloat16 hi, lo; split_bf16(v, hi, lo);
    g_w3_h[i] = hi; g_w3_l[i] = lo;
}
// transpose + split features: F[b][c][hw] -> g_fT[b*196+hw][c]
__global__ void cvt_f(const float* __restrict__ f2, const float* __restrict__ f3) {
    __shared__ float t[32][33];
    int hw0 = blockIdx.x * 32, c0 = blockIdx.y * 32, b = blockIdx.z;
    const float* F = (b < HB) ? f2 + (size_t)b * CIN * HW
                              : f3 + (size_t)(b - HB) * CIN * HW;
    int tx = threadIdx.x, ty = threadIdx.y;
    #pragma unroll
    for (int k = 0; k < 4; k++) {
        int cc = c0 + ty + k * 8, hw = hw0 + tx;
        t[ty + k * 8][tx] = (hw < HW) ? F[(size_t)cc * HW + hw] : 0.f;
    }
    __syncthreads();
    #pragma unroll
    for (int k = 0; k < 4; k++) {
        int hw = hw0 + ty + k * 8;
        if (hw < HW) {
            float v = t[tx][ty + k * 8];
            __nv_bfloat16 hi, lo; split_bf16(v, hi, lo);
            size_t idx = ((size_t)b * HW + hw) * CIN + c0 + tx;
            g_fT_h[idx] = hi; g_fT_l[idx] = lo;
        }
    }
}

// ---------------- K1: reduce GEMM (M=512, N=25088, K=2048) + BN/ReLU --------
__global__ __launch_bounds__(256, 2) void k_reduce_mma() {
    GEMM_VARS();
    int n0 = blockIdx.x * 128, m0 = blockIdx.y * 128;
    const int T = CIN / 32;    // 64 stages
    const __nv_bfloat16* Awh = g_w1_h + (size_t)m0 * CIN;
    const __nv_bfloat16* Awl = g_w1_l + (size_t)m0 * CIN;
    const __nv_bfloat16* Bfh = g_fT_h + (size_t)n0 * CIN;
    const __nv_bfloat16* Bfl = g_fT_l + (size_t)n0 * CIN;
    #define ISSUE(kt) {                                                        \
        uint32_t s = sb0 + ((kt) & 1) * STAGE_B; int k0 = (kt) * 32;           \
        cpa_tile(s,              Awh, CIN, k0, tid);                           \
        cpa_tile(s + TILE_B,     Awl, CIN, k0, tid);                           \
        cpa_tile(s + 2 * TILE_B, Bfh, CIN, k0, tid);                           \
        cpa_tile(s + 3 * TILE_B, Bfl, CIN, k0, tid); }
    ISSUE(0); cp_commit();
    for (int kt = 0; kt < T; kt++) {
        if (kt + 1 < T) { ISSUE(kt + 1); cp_commit(); cp_wait<1>(); }
        else cp_wait<0>();
        __syncthreads();
        stage_compute(sb0 + (kt & 1) * STAGE_B, wm, wn, lane, c);
        __syncthreads();
    }
    #undef ISSUE
    #pragma unroll
    for (int am = 0; am < 4; am++) {
        #pragma unroll
        for (int half = 0; half < 2; half++) {
            int o = m0 + wm + am * 16 + (lane >> 2) + half * 8;
            float sc = g_scale1[o], sh = g_shift1[o];
            #pragma unroll
            for (int bn = 0; bn < 4; bn++) {
                #pragma unroll
                for (int e = 0; e < 2; e++) {
                    float v = c[am][bn][half * 2 + e];
                    v = fmaxf(v * sc + sh, 0.f);
                    int col = n0 + wn + bn * 8 + 2 * (lane & 3) + e;
                    int b = col / HW, hw = col - b * HW;
                    __nv_bfloat16 hi, lo; split_bf16(v, hi, lo);
                    size_t i1 = ((size_t)b * CMID + o) * HWP + hw;
                    g_x_h[i1] = hi; g_x_l[i1] = lo;
                    size_t i2 = ((size_t)b * HW + hw) * CMID + o;
                    g_xT_h[i2] = hi; g_xT_l[i2] = lo;
                }
            }
        }
    }
}

// ---------------- K2: XXt per batch (M=N=512, K=196 pad 256) ----------------
__global__ __launch_bounds__(256, 2) void k_xxt_mma() {
    GEMM_VARS();
    int n0 = blockIdx.x * 128, m0 = blockIdx.y * 128, b = blockIdx.z;
    const __nv_bfloat16* Xh = g_x_h + (size_t)b * CMID * HWP;
    const __nv_bfloat16* Xl = g_x_l + (size_t)b * CMID * HWP;
    const int T = HWP / 32;    // 8 stages
    #define ISSUE(kt) {                                                        \
        uint32_t s = sb0 + ((kt) & 1) * STAGE_B; int k0 = (kt) * 32;           \
        cpa_tile(s,              Xh + (size_t)m0 * HWP, HWP, k0, tid);         \
        cpa_tile(s + TILE_B,     Xl + (size_t)m0 * HWP, HWP, k0, tid);         \
        cpa_tile(s + 2 * TILE_B, Xh + (size_t)n0 * HWP, HWP, k0, tid);         \
        cpa_tile(s + 3 * TILE_B, Xl + (size_t)n0 * HWP, HWP, k0, tid); }
    ISSUE(0); cp_commit();
    for (int kt = 0; kt < T; kt++) {
        if (kt + 1 < T) { ISSUE(kt + 1); cp_commit(); cp_wait<1>(); }
        else cp_wait<0>();
        __syncthreads();
        stage_compute(sb0 + (kt & 1) * STAGE_B, wm, wn, lane, c);
        __syncthreads();
    }
    #undef ISSUE
    float* out = g_att + (size_t)b * CMID * CMID;
    #pragma unroll
    for (int am = 0; am < 4; am++)
        #pragma unroll
        for (int half = 0; half < 2; half++) {
            int r = m0 + wm + am * 16 + (lane >> 2) + half * 8;
            #pragma unroll
            for (int bn = 0; bn < 4; bn++) {
                int col = n0 + wn + bn * 8 + 2 * (lane & 3);
                out[(size_t)r * CMID + col]     = c[am][bn][half * 2 + 0];
                out[(size_t)r * CMID + col + 1] = c[am][bn][half * 2 + 1];
            }
        }
}

// ---------------- K3: softmax(-S) rowwise -> bf16 hi/lo ---------------------
__global__ __launch_bounds__(256) void k_softmax() {
    int gw = (blockIdx.x * blockDim.x + threadIdx.x) >> 5;
    int lane = threadIdx.x & 31;
    if (gw >= BATCH * CMID) return;
    const float* row = g_att + (size_t)gw * CMID;
    float mn = CUDART_INF_F;
    #pragma unroll
    for (int t = 0; t < 16; t++) mn = fminf(mn, row[lane + t * 32]);
    #pragma unroll
    for (int o = 16; o; o >>= 1) mn = fminf(mn, __shfl_xor_sync(~0u, mn, o));
    float e[16], sum = 0.f;
    #pragma unroll
    for (int t = 0; t < 16; t++) { e[t] = __expf(mn - row[lane + t * 32]); sum += e[t]; }
    #pragma unroll
    for (int o = 16; o; o >>= 1) sum += __shfl_xor_sync(~0u, sum, o);
    float inv = 1.f / sum;
    #pragma unroll
    for (int t = 0; t < 16; t++) {
        float v = e[t] * inv;
        __nv_bfloat16 hi, lo; split_bf16(v, hi, lo);
        size_t i = (size_t)gw * CMID + lane + t * 32;
        g_att_h[i] = hi; g_att_l[i] = lo;
    }
}

// ---------------- K4: y = att @ X^T-layout (M=512, N=196pad256, K=512) ------
__global__ __launch_bounds__(256, 2) void k_ygemm_mma() {
    GEMM_VARS();
    int n0 = blockIdx.x * 128, m0 = blockIdx.y * 128, b = blockIdx.z;
    const __nv_bfloat16* Ah = g_att_h + ((size_t)b * CMID + m0) * CMID;
    const __nv_bfloat16* Al = g_att_l + ((size_t)b * CMID + m0) * CMID;
    const __nv_bfloat16* Bh = g_xT_h + (size_t)b * HW * CMID;
    const __nv_bfloat16* Bl = g_xT_l + (size_t)b * HW * CMID;
    const int T = CMID / 32;   // 16 stages
    #define ISSUE(kt) {                                                        \
        uint32_t s = sb0 + ((kt) & 1) * STAGE_B; int k0 = (kt) * 32;           \
        cpa_tile(s,          Ah, CMID, k0, tid);                               \
        cpa_tile(s + TILE_B, Al, CMID, k0, tid);                               \
        cpa_tile_clamp(s + 2 * TILE_B, Bh, CMID, n0, HW - 1, k0, tid);         \
        cpa_tile_clamp(s + 3 * TILE_B, Bl, CMID, n0, HW - 1, k0, tid); }
    ISSUE(0); cp_commit();
    for (int kt = 0; kt < T; kt++) {
        if (kt + 1 < T) { ISSUE(kt + 1); cp_commit(); cp_wait<1>(); }
        else cp_wait<0>();
        __syncthreads();
        stage_compute(sb0 + (kt & 1) * STAGE_B, wm, wn, lane, c);
        __syncthreads();
    }
    #undef ISSUE
    #pragma unroll
    for (int am = 0; am < 4; am++)
        #pragma unroll
        for (int half = 0; half < 2; half++) {
            int i = m0 + wm + am * 16 + (lane >> 2) + half * 8;
            #pragma unroll
            for (int bn = 0; bn < 4; bn++)
                #pragma unroll
                for (int e = 0; e < 2; e++) {
                    int col = n0 + wn + bn * 8 + 2 * (lane & 3) + e;
                    if (col < HW) {
                        __nv_bfloat16 hi, lo;
                        split_bf16(c[am][bn][half * 2 + e], hi, lo);
                        size_t idx = ((size_t)b * HW + col) * CMID + i;
                        g_yT_h[idx] = hi; g_yT_l[idx] = lo;
                    }
                }
        }
}

// ---------------- K5: conv3 implicit GEMM (M=512, N=25088, K=4608) ----------
// K reordered (rs, c): stage kt -> rs = kt/16, c0 = (kt%16)*32
__global__ __launch_bounds__(256, 2) void k_conv_mma() {
    GEMM_VARS();
    int n0 = blockIdx.x * 128, m0 = blockIdx.y * 128;
    const int T = K33 / 32;    // 144 stages
    // the 2 gather rows this thread serves: tid>>2 and 64+(tid>>2)
    int gr[2], gb[2], gph[2], gpw[2];
    #pragma unroll
    for (int it = 0; it < 2; it++) {
        int row = it * 64 + (tid >> 2);
        gr[it] = row;
        int col = n0 + row;
        gb[it] = col / HW;
        int p = col - gb[it] * HW;
        gph[it] = p / 14; gpw[it] = p - gph[it] * 14;
    }
    int seg = tid & 3;
    #define ISSUE(kt) {                                                        \
        uint32_t s = sb0 + ((kt) & 1) * STAGE_B; int k0 = (kt) * 32;           \
        cpa_tile(s,          g_w3_h + (size_t)m0 * K33, K33, k0, tid);         \
        cpa_tile(s + TILE_B, g_w3_l + (size_t)m0 * K33, K33, k0, tid);         \
        int rs = (kt) >> 4, c0 = ((kt) & 15) * 32;                             \
        int dr = rs / 3 - 1, ds = rs - (rs / 3) * 3 - 1;                       \
        _Pragma("unroll")                                                      \
        for (int it = 0; it < 2; it++) {                                       \
            int ih = gph[it] + dr, iw = gpw[it] + ds;                          \
            int ok = ((unsigned)ih < 14u) && ((unsigned)iw < 14u);             \
            size_t pix = (size_t)gb[it] * HW + (ok ? ih * 14 + iw : 0);        \
            size_t gidx = pix * CMID + c0 + seg * 8;                           \
            uint32_t sa = gr[it] * TROW + seg * 16;                            \
            cp16z(s + 2 * TILE_B + sa, g_yT_h + gidx, ok);                     \
            cp16z(s + 3 * TILE_B + sa, g_yT_l + gidx, ok);                     \
        } }
    ISSUE(0); cp_commit();
    for (int kt = 0; kt < T; kt++) {
        if (kt + 1 < T) { ISSUE(kt + 1); cp_commit(); cp_wait<1>(); }
        else cp_wait<0>();
        __syncthreads();
        stage_compute(sb0 + (kt & 1) * STAGE_B, wm, wn, lane, c);
        __syncthreads();
    }
    #undef ISSUE
    // fused BN + ReLU + GAP (sum into g_zsum via quad-reduced atomics)
    int b0 = n0 / HW;
    int split = (b0 + 1) * HW - n0;   // local cols < split belong to b0
    #pragma unroll
    for (int am = 0; am < 4; am++)
        #pragma unroll
        for (int half = 0; half < 2; half++) {
            int o = m0 + wm + am * 16 + (lane >> 2) + half * 8;
            float sc = g_scale3[o], sh = g_shift3[o];
            float s0 = 0.f, s1 = 0.f;
            #pragma unroll
            for (int bn = 0; bn < 4; bn++)
                #pragma unroll
                for (int e = 0; e < 2; e++) {
                    float v = fmaxf(c[am][bn][half * 2 + e] * sc + sh, 0.f);
                    int lcol = wn + bn * 8 + 2 * (lane & 3) + e;
                    if (lcol < split) s0 += v; else s1 += v;
                }
            s0 += __shfl_xor_sync(~0u, s0, 1);
            s0 += __shfl_xor_sync(~0u, s0, 2);
            s1 += __shfl_xor_sync(~0u, s1, 1);
            s1 += __shfl_xor_sync(~0u, s1, 2);
            if ((lane & 3) == 0) {
                atomicAdd(&g_zsum[b0 * CMID + o], s0 * (1.f / HW));
                if (split < 128)
                    atomicAdd(&g_zsum[(b0 + 1) * CMID + o], s1 * (1.f / HW));
            }
        }
}

// ---------------- K7: fc1 + ReLU --------------------------------------------
__global__ __launch_bounds__(256) void k_fc1(const float* __restrict__ w,
                                             const float* __restrict__ bias) {
    int gw = (blockIdx.x * blockDim.x + threadIdx.x) >> 5;
    int lane = threadIdx.x & 31;
    if (gw >= BATCH * 200) return;
    int b = gw / 200, j = gw - b * 200;
    const float* zr = g_zsum + b * CMID;
    const float* wr = w + (size_t)j * CMID;
    float s = 0.f;
    for (int k = lane; k < CMID; k += 32) s += zr[k] * wr[k];
    #pragma unroll
    for (int o = 16; o; o >>= 1) s += __shfl_xor_sync(~0u, s, o);
    if (lane == 0) g_h[gw] = fmaxf(s + bias[j], 0.f);
}

// ---------------- K8: fc2 + branch-sum --------------------------------------
__global__ __launch_bounds__(256) void k_fc2(const float* __restrict__ w,
                                             const float* __restrict__ bias,
                                             float* __restrict__ out) {
    int gw = (blockIdx.x * blockDim.x + threadIdx.x) >> 5;
    int lane = threadIdx.x & 31;
    if (gw >= HB * 200) return;
    int b = gw / 200, j = gw - b * 200;
    const float* h1 = g_h + (size_t)b * 200;
    const float* h2 = g_h + (size_t)(b + HB) * 200;
    const float* wr = w + (size_t)j * 200;
    float s = 0.f;
    for (int k = lane; k < 200; k += 32) s += (h1[k] + h2[k]) * wr[k];
    #pragma unroll
    for (int o = 16; o; o >>= 1) s += __shfl_xor_sync(~0u, s, o);
    if (lane == 0) out[gw] = s + 2.f * bias[j];
}

// ---------------- launch ----------------------------------------------------
extern "C" void kernel_launch(void* const* d_in, const int* in_sizes, int n_in,
                              void* d_out, int out_size) {
    const float* f2  = (const float*)d_in[0];
    const float* f3  = (const float*)d_in[1];
    const float* rw  = (const float*)d_in[2];
    const float* rb  = (const float*)d_in[3];
    const float* rg  = (const float*)d_in[4];
    const float* rbe = (const float*)d_in[5];
    const float* rm  = (const float*)d_in[6];
    const float* rv  = (const float*)d_in[7];
    const float* c3w = (const float*)d_in[8];
    const float* c3b = (const float*)d_in[9];
    const float* c3g = (const float*)d_in[10];
    const float* c3be= (const float*)d_in[11];
    const float* c3m = (const float*)d_in[12];
    const float* c3v = (const float*)d_in[13];
    const float* f1w = (const float*)d_in[14];
    const float* f1b = (const float*)d_in[15];
    const float* f2w = (const float*)d_in[16];
    const float* f2b = (const float*)d_in[17];
    float* out = (float*)d_out;

    cudaFuncSetAttribute(k_reduce_mma, cudaFuncAttributeMaxDynamicSharedMemorySize, DYN_SMEM);
    cudaFuncSetAttribute(k_xxt_mma,    cudaFuncAttributeMaxDynamicSharedMemorySize, DYN_SMEM);
    cudaFuncSetAttribute(k_ygemm_mma,  cudaFuncAttributeMaxDynamicSharedMemorySize, DYN_SMEM);
    cudaFuncSetAttribute(k_conv_mma,   cudaFuncAttributeMaxDynamicSharedMemorySize, DYN_SMEM);

    k_zero<<<BATCH * CMID / 256, 256>>>();
    prep_bn<<<2, 256>>>(rb, rg, rbe, rm, rv, c3b, c3g, c3be, c3m, c3v);
    cvt_w1<<<(CMID * CIN) / 256, 256>>>(rw);
    cvt_w3<<<(CMID * K33) / 256, 256>>>(c3w);
    cvt_f<<<dim3(7, CIN / 32, BATCH), dim3(32, 8)>>>(f2, f3);

    k_reduce_mma<<<dim3(NFLAT / 128, 4), 256, DYN_SMEM>>>();
    k_xxt_mma<<<dim3(4, 4, BATCH), 256, DYN_SMEM>>>();
    k_softmax<<<(BATCH * CMID) / 8, 256>>>();
    k_ygemm_mma<<<dim3(2, 4, BATCH), 256, DYN_SMEM>>>();
    k_conv_mma<<<dim3(NFLAT / 128, 4), 256, DYN_SMEM>>>();
    k_fc1<<<(BATCH * 200 + 7) / 8, 256>>>(f1w, f1b);
    k_fc2<<<(HB * 200 + 7) / 8, 256>>>(f2w, f2b, out);
}

// round 7
// speedup vs baseline: 4.4988x; 1.2160x over previous
#include <cuda_runtime.h>
#include <cuda_bf16.h>
#include <cstdint>
#include <math_constants.h>

#define EPS 1e-5f
#define HB 64
#define BATCH 128
#define CIN 2048
#define CMID 512
#define HW 196
#define HWP 256
#define K33 4608
#define NFLAT 25088   // 128*196 = 196 tiles of 128 exactly

// ---------------- scratch (static device globals; zero-init at load) --------
__device__ __nv_bfloat16 g_fT_h[(size_t)NFLAT * CIN];
__device__ __nv_bfloat16 g_fT_l[(size_t)NFLAT * CIN];
__device__ __nv_bfloat16 g_x_h [(size_t)BATCH * CMID * HWP];  // pad cols stay 0
__device__ __nv_bfloat16 g_x_l [(size_t)BATCH * CMID * HWP];
__device__ __nv_bfloat16 g_xT_h[(size_t)BATCH * HW * CMID];
__device__ float         g_att [(size_t)BATCH * CMID * CMID];
__device__ __nv_bfloat16 g_att_h[(size_t)BATCH * CMID * CMID];
__device__ __nv_bfloat16 g_att_l[(size_t)BATCH * CMID * CMID];
__device__ __nv_bfloat16 g_yT_h[(size_t)BATCH * HW * CMID];
__device__ __nv_bfloat16 g_w1_h[(size_t)CMID * CIN];
__device__ __nv_bfloat16 g_w1_l[(size_t)CMID * CIN];
__device__ __nv_bfloat16 g_w3_h[(size_t)CMID * K33];   // reordered k = rs*512 + c
__device__ __nv_bfloat16 g_w3_l[(size_t)CMID * K33];
__device__ float g_zsum[BATCH * CMID];
__device__ float g_h[BATCH * 200];
__device__ float g_scale1[CMID], g_shift1[CMID], g_scale3[CMID], g_shift3[CMID];

// ---------------- ptx helpers (all non-'a' gated: sm_80-level) --------------
__device__ __forceinline__ uint32_t smem_u32(const void* p) {
    uint32_t a;
    asm("{ .reg .u64 t; cvta.to.shared.u64 t, %1; cvt.u32.u64 %0, t; }"
        : "=r"(a) : "l"(p));
    return a;
}
__device__ __forceinline__ void cp16(uint32_t dst, const void* src) {
    asm volatile("cp.async.ca.shared.global [%0], [%1], 16;"
                 :: "r"(dst), "l"(src));
}
__device__ __forceinline__ void cp16z(uint32_t dst, const void* src, int ok) {
    int sz = ok ? 16 : 0;
    asm volatile("cp.async.ca.shared.global [%0], [%1], 16, %2;"
                 :: "r"(dst), "l"(src), "r"(sz));
}
__device__ __forceinline__ void cp_commit() {
    asm volatile("cp.async.commit_group;" ::: "memory");
}
template<int N> __device__ __forceinline__ void cp_wait() {
    asm volatile("cp.async.wait_group %0;" :: "n"(N) : "memory");
}
__device__ __forceinline__ void ldm4(uint32_t* r, uint32_t addr) {
    asm volatile("ldmatrix.sync.aligned.m8n8.x4.shared.b16 {%0,%1,%2,%3}, [%4];"
                 : "=r"(r[0]), "=r"(r[1]), "=r"(r[2]), "=r"(r[3]) : "r"(addr));
}
__device__ __forceinline__ void ldm2(uint32_t* r, uint32_t addr) {
    asm volatile("ldmatrix.sync.aligned.m8n8.x2.shared.b16 {%0,%1}, [%2];"
                 : "=r"(r[0]), "=r"(r[1]) : "r"(addr));
}
__device__ __forceinline__ void mma16816(float* c, const uint32_t* a,
                                         const uint32_t* b) {
    asm volatile(
        "mma.sync.aligned.m16n8k16.row.col.f32.bf16.bf16.f32 "
        "{%0,%1,%2,%3}, {%4,%5,%6,%7}, {%8,%9}, {%0,%1,%2,%3};"
        : "+f"(c[0]), "+f"(c[1]), "+f"(c[2]), "+f"(c[3])
        : "r"(a[0]), "r"(a[1]), "r"(a[2]), "r"(a[3]), "r"(b[0]), "r"(b[1]));
}
__device__ __forceinline__ void split_bf16(float v, __nv_bfloat16& hi,
                                           __nv_bfloat16& lo) {
    hi = __float2bfloat16(v);
    lo = __float2bfloat16(v - __bfloat162float(hi));
}

// ---------------- SMEM geometry ---------------------------------------------
#define TROW 80
#define TILE_B (128 * TROW)          // 10240 B
#define STAGE_B (4 * TILE_B)         // Ah, Al, Bh, Bl = 40960 B (reduce/xxt)
#define STAGE3_B (3 * TILE_B)        // Ah, Al, Bh     = 30720 B (ygemm/conv)
#define DYN_SMEM (2 * STAGE_B)       // 81920 B
#define DYN3_SMEM (2 * STAGE3_B)     // 61440 B

// contiguous 128x32 tile load via cp.async: 512 16B chunks / 256 threads
__device__ __forceinline__ void cpa_tile(uint32_t sdst, const __nv_bfloat16* g,
                                         size_t stride, int k0, int tid) {
    #pragma unroll
    for (int it = 0; it < 2; it++) {
        int ch = it * 256 + tid;
        int row = ch >> 2, seg = ch & 3;
        cp16(sdst + row * TROW + seg * 16,
             g + (size_t)row * stride + k0 + seg * 8);
    }
}
__device__ __forceinline__ void cpa_tile_clamp(uint32_t sdst,
                                               const __nv_bfloat16* g,
                                               size_t stride, int row0,
                                               int maxrow, int k0, int tid) {
    #pragma unroll
    for (int it = 0; it < 2; it++) {
        int ch = it * 256 + tid;
        int row = ch >> 2, seg = ch & 3;
        int rg = row0 + row; if (rg > maxrow) rg = maxrow;
        cp16(sdst + row * TROW + seg * 16,
             g + (size_t)rg * stride + k0 + seg * 8);
    }
}

// one k16 slab: 4 m-atoms x 4 n-atoms of m16n8k16
__device__ __forceinline__ void mma_k16(uint32_t aBase, uint32_t bBase, int kk,
                                        int lane, float c[4][4][4]) {
    uint32_t a[4][4], b[4][2];
    int arow = lane & 15, asel = lane >> 4;
    #pragma unroll
    for (int am = 0; am < 4; am++)
        ldm4(a[am], aBase + (am * 16 + arow) * TROW + (kk + asel * 8) * 2);
    int brow = lane & 7, bsel = (lane >> 3) & 1;
    #pragma unroll
    for (int bn = 0; bn < 4; bn++)
        ldm2(b[bn], bBase + (bn * 8 + brow) * TROW + (kk + bsel * 8) * 2);
    #pragma unroll
    for (int am = 0; am < 4; am++)
        #pragma unroll
        for (int bn = 0; bn < 4; bn++)
            mma16816(c[am][bn], a[am], b[bn]);
}

// 2-A variant: (Ahi + Alo) x B, B fragments loaded once
__device__ __forceinline__ void mma_k16_2A(uint32_t aH, uint32_t aL,
                                           uint32_t bBase, int kk, int lane,
                                           float c[4][4][4]) {
    uint32_t a[4][4], b[4][2];
    int arow = lane & 15, asel = lane >> 4;
    int brow = lane & 7, bsel = (lane >> 3) & 1;
    #pragma unroll
    for (int bn = 0; bn < 4; bn++)
        ldm2(b[bn], bBase + (bn * 8 + brow) * TROW + (kk + bsel * 8) * 2);
    #pragma unroll
    for (int am = 0; am < 4; am++)
        ldm4(a[am], aH + (am * 16 + arow) * TROW + (kk + asel * 8) * 2);
    #pragma unroll
    for (int am = 0; am < 4; am++)
        #pragma unroll
        for (int bn = 0; bn < 4; bn++)
            mma16816(c[am][bn], a[am], b[bn]);
    #pragma unroll
    for (int am = 0; am < 4; am++)
        ldm4(a[am], aL + (am * 16 + arow) * TROW + (kk + asel * 8) * 2);
    #pragma unroll
    for (int am = 0; am < 4; am++)
        #pragma unroll
        for (int bn = 0; bn < 4; bn++)
            mma16816(c[am][bn], a[am], b[bn]);
}

// full 3-term stage (reduce/xxt): (Ah,Bh), (Ah,Bl), (Al,Bh)
__device__ __forceinline__ void stage_compute(uint32_t sb, int wm, int wn,
                                              int lane, float c[4][4][4]) {
    uint32_t Ah = sb + wm * TROW,            Al = Ah + TILE_B;
    uint32_t Bh = sb + 2 * TILE_B + wn * TROW, Bl = Bh + TILE_B;
    #pragma unroll
    for (int kk = 0; kk < 32; kk += 16) {
        mma_k16(Ah, Bh, kk, lane, c);
        mma_k16(Ah, Bl, kk, lane, c);
        mma_k16(Al, Bh, kk, lane, c);
    }
}
// 2-term stage (ygemm/conv): (Ah + Al) x Bh
__device__ __forceinline__ void stage_compute_2A(uint32_t sb, int wm, int wn,
                                                 int lane, float c[4][4][4]) {
    uint32_t Ah = sb + wm * TROW, Al = Ah + TILE_B;
    uint32_t Bh = sb + 2 * TILE_B + wn * TROW;
    #pragma unroll
    for (int kk = 0; kk < 32; kk += 16) mma_k16_2A(Ah, Al, Bh, kk, lane, c);
}

#define GEMM_VARS()                                                            \
    extern __shared__ __align__(16) char dsm[];                                \
    uint32_t sb0 = smem_u32(dsm);                                              \
    int tid = threadIdx.x, wid = tid >> 5, lane = tid & 31;                    \
    int wm = (wid >> 2) * 64, wn = (wid & 3) * 32;                             \
    float c[4][4][4] = {};

// ---------------- small prep kernels ----------------------------------------
__global__ void k_zero() {
    g_zsum[blockIdx.x * blockDim.x + threadIdx.x] = 0.f;
}
__global__ void prep_bn(const float* __restrict__ rb, const float* __restrict__ rg,
                        const float* __restrict__ rbe, const float* __restrict__ rm,
                        const float* __restrict__ rv,
                        const float* __restrict__ cb, const float* __restrict__ cg,
                        const float* __restrict__ cbe, const float* __restrict__ cm,
                        const float* __restrict__ cv) {
    int i = blockIdx.x * blockDim.x + threadIdx.x;
    if (i < CMID) {
        float inv = rg[i] * rsqrtf(rv[i] + EPS);
        g_scale1[i] = inv;
        g_shift1[i] = (rb[i] - rm[i]) * inv + rbe[i];
        float inv3 = cg[i] * rsqrtf(cv[i] + EPS);
        g_scale3[i] = inv3;
        g_shift3[i] = (cb[i] - cm[i]) * inv3 + cbe[i];
    }
}
__global__ void cvt_w1(const float* __restrict__ w) {
    int i = blockIdx.x * blockDim.x + threadIdx.x;
    __nv_bfloat16 hi, lo; split_bf16(w[i], hi, lo);
    g_w1_h[i] = hi; g_w1_l[i] = lo;
}
__global__ void cvt_w3(const float* __restrict__ w) {
    int i = blockIdx.x * blockDim.x + threadIdx.x;   // over 512*4608
    int o = i / K33, k = i - o * K33;
    int rs = k >> 9, cc = k & 511;
    int r = rs / 3, s = rs - r * 3;
    float v = w[((o * CMID + cc) * 3 + r) * 3 + s];
    __nv_bfloat16 hi, lo; split_bf16(v, hi, lo);
    g_w3_h[i] = hi; g_w3_l[i] = lo;
}
// transpose + split features: F[b][c][hw] -> g_fT[b*196+hw][c]
__global__ void cvt_f(const float* __restrict__ f2, const float* __restrict__ f3) {
    __shared__ float t[32][33];
    int hw0 = blockIdx.x * 32, c0 = blockIdx.y * 32, b = blockIdx.z;
    const float* F = (b < HB) ? f2 + (size_t)b * CIN * HW
                              : f3 + (size_t)(b - HB) * CIN * HW;
    int tx = threadIdx.x, ty = threadIdx.y;
    #pragma unroll
    for (int k = 0; k < 4; k++) {
        int cc = c0 + ty + k * 8, hw = hw0 + tx;
        t[ty + k * 8][tx] = (hw < HW) ? F[(size_t)cc * HW + hw] : 0.f;
    }
    __syncthreads();
    #pragma unroll
    for (int k = 0; k < 4; k++) {
        int hw = hw0 + ty + k * 8;
        if (hw < HW) {
            float v = t[tx][ty + k * 8];
            __nv_bfloat16 hi, lo; split_bf16(v, hi, lo);
            size_t idx = ((size_t)b * HW + hw) * CIN + c0 + tx;
            g_fT_h[idx] = hi; g_fT_l[idx] = lo;
        }
    }
}

// ---------------- K1: reduce GEMM (M=512, N=25088, K=2048) + BN/ReLU --------
// grid (4 m, 196 n): m fastest -> 4 consecutive CTAs share each B tile in L2
__global__ __launch_bounds__(256, 2) void k_reduce_mma() {
    GEMM_VARS();
    int m0 = blockIdx.x * 128, n0 = blockIdx.y * 128;
    const int T = CIN / 32;    // 64 stages
    const __nv_bfloat16* Awh = g_w1_h + (size_t)m0 * CIN;
    const __nv_bfloat16* Awl = g_w1_l + (size_t)m0 * CIN;
    const __nv_bfloat16* Bfh = g_fT_h + (size_t)n0 * CIN;
    const __nv_bfloat16* Bfl = g_fT_l + (size_t)n0 * CIN;
    #define ISSUE(kt) {                                                        \
        uint32_t s = sb0 + ((kt) & 1) * STAGE_B; int k0 = (kt) * 32;           \
        cpa_tile(s,              Awh, CIN, k0, tid);                           \
        cpa_tile(s + TILE_B,     Awl, CIN, k0, tid);                           \
        cpa_tile(s + 2 * TILE_B, Bfh, CIN, k0, tid);                           \
        cpa_tile(s + 3 * TILE_B, Bfl, CIN, k0, tid); }
    ISSUE(0); cp_commit();
    for (int kt = 0; kt < T; kt++) {
        if (kt + 1 < T) { ISSUE(kt + 1); cp_commit(); cp_wait<1>(); }
        else cp_wait<0>();
        __syncthreads();
        stage_compute(sb0 + (kt & 1) * STAGE_B, wm, wn, lane, c);
        __syncthreads();
    }
    #undef ISSUE
    #pragma unroll
    for (int am = 0; am < 4; am++) {
        #pragma unroll
        for (int half = 0; half < 2; half++) {
            int o = m0 + wm + am * 16 + (lane >> 2) + half * 8;
            float sc = g_scale1[o], sh = g_shift1[o];
            #pragma unroll
            for (int bn = 0; bn < 4; bn++) {
                #pragma unroll
                for (int e = 0; e < 2; e++) {
                    float v = c[am][bn][half * 2 + e];
                    v = fmaxf(v * sc + sh, 0.f);
                    int col = n0 + wn + bn * 8 + 2 * (lane & 3) + e;
                    int b = col / HW, hw = col - b * HW;
                    __nv_bfloat16 hi, lo; split_bf16(v, hi, lo);
                    size_t i1 = ((size_t)b * CMID + o) * HWP + hw;
                    g_x_h[i1] = hi; g_x_l[i1] = lo;
                    g_xT_h[((size_t)b * HW + hw) * CMID + o] = hi;
                }
            }
        }
    }
}

// ---------------- K2: XXt per batch (M=N=512, K=196 pad 256) ----------------
__global__ __launch_bounds__(256, 2) void k_xxt_mma() {
    GEMM_VARS();
    int n0 = blockIdx.x * 128, m0 = blockIdx.y * 128, b = blockIdx.z;
    const __nv_bfloat16* Xh = g_x_h + (size_t)b * CMID * HWP;
    const __nv_bfloat16* Xl = g_x_l + (size_t)b * CMID * HWP;
    const int T = HWP / 32;    // 8 stages
    #define ISSUE(kt) {                                                        \
        uint32_t s = sb0 + ((kt) & 1) * STAGE_B; int k0 = (kt) * 32;           \
        cpa_tile(s,              Xh + (size_t)m0 * HWP, HWP, k0, tid);         \
        cpa_tile(s + TILE_B,     Xl + (size_t)m0 * HWP, HWP, k0, tid);         \
        cpa_tile(s + 2 * TILE_B, Xh + (size_t)n0 * HWP, HWP, k0, tid);         \
        cpa_tile(s + 3 * TILE_B, Xl + (size_t)n0 * HWP, HWP, k0, tid); }
    ISSUE(0); cp_commit();
    for (int kt = 0; kt < T; kt++) {
        if (kt + 1 < T) { ISSUE(kt + 1); cp_commit(); cp_wait<1>(); }
        else cp_wait<0>();
        __syncthreads();
        stage_compute(sb0 + (kt & 1) * STAGE_B, wm, wn, lane, c);
        __syncthreads();
    }
    #undef ISSUE
    float* out = g_att + (size_t)b * CMID * CMID;
    #pragma unroll
    for (int am = 0; am < 4; am++)
        #pragma unroll
        for (int half = 0; half < 2; half++) {
            int r = m0 + wm + am * 16 + (lane >> 2) + half * 8;
            #pragma unroll
            for (int bn = 0; bn < 4; bn++) {
                int col = n0 + wn + bn * 8 + 2 * (lane & 3);
                out[(size_t)r * CMID + col]     = c[am][bn][half * 2 + 0];
                out[(size_t)r * CMID + col + 1] = c[am][bn][half * 2 + 1];
            }
        }
}

// ---------------- K3: softmax(-S) rowwise -> bf16 hi/lo ---------------------
__global__ __launch_bounds__(256) void k_softmax() {
    int gw = (blockIdx.x * blockDim.x + threadIdx.x) >> 5;
    int lane = threadIdx.x & 31;
    if (gw >= BATCH * CMID) return;
    const float* row = g_att + (size_t)gw * CMID;
    float mn = CUDART_INF_F;
    #pragma unroll
    for (int t = 0; t < 16; t++) mn = fminf(mn, row[lane + t * 32]);
    #pragma unroll
    for (int o = 16; o; o >>= 1) mn = fminf(mn, __shfl_xor_sync(~0u, mn, o));
    float e[16], sum = 0.f;
    #pragma unroll
    for (int t = 0; t < 16; t++) { e[t] = __expf(mn - row[lane + t * 32]); sum += e[t]; }
    #pragma unroll
    for (int o = 16; o; o >>= 1) sum += __shfl_xor_sync(~0u, sum, o);
    float inv = 1.f / sum;
    #pragma unroll
    for (int t = 0; t < 16; t++) {
        float v = e[t] * inv;
        __nv_bfloat16 hi, lo; split_bf16(v, hi, lo);
        size_t i = (size_t)gw * CMID + lane + t * 32;
        g_att_h[i] = hi; g_att_l[i] = lo;
    }
}

// ---------------- K4: y = att @ X (M=512, N=196pad256, K=512), 2-term -------
__global__ __launch_bounds__(256, 2) void k_ygemm_mma() {
    GEMM_VARS();
    int n0 = blockIdx.x * 128, m0 = blockIdx.y * 128, b = blockIdx.z;
    const __nv_bfloat16* Ah = g_att_h + ((size_t)b * CMID + m0) * CMID;
    const __nv_bfloat16* Al = g_att_l + ((size_t)b * CMID + m0) * CMID;
    const __nv_bfloat16* Bh = g_xT_h + (size_t)b * HW * CMID;
    const int T = CMID / 32;   // 16 stages
    #define ISSUE(kt) {                                                        \
        uint32_t s = sb0 + ((kt) & 1) * STAGE3_B; int k0 = (kt) * 32;          \
        cpa_tile(s,          Ah, CMID, k0, tid);                               \
        cpa_tile(s + TILE_B, Al, CMID, k0, tid);                               \
        cpa_tile_clamp(s + 2 * TILE_B, Bh, CMID, n0, HW - 1, k0, tid); }
    ISSUE(0); cp_commit();
    for (int kt = 0; kt < T; kt++) {
        if (kt + 1 < T) { ISSUE(kt + 1); cp_commit(); cp_wait<1>(); }
        else cp_wait<0>();
        __syncthreads();
        stage_compute_2A(sb0 + (kt & 1) * STAGE3_B, wm, wn, lane, c);
        __syncthreads();
    }
    #undef ISSUE
    #pragma unroll
    for (int am = 0; am < 4; am++)
        #pragma unroll
        for (int half = 0; half < 2; half++) {
            int i = m0 + wm + am * 16 + (lane >> 2) + half * 8;
            #pragma unroll
            for (int bn = 0; bn < 4; bn++)
                #pragma unroll
                for (int e = 0; e < 2; e++) {
                    int col = n0 + wn + bn * 8 + 2 * (lane & 3) + e;
                    if (col < HW)
                        g_yT_h[((size_t)b * HW + col) * CMID + i] =
                            __float2bfloat16(c[am][bn][half * 2 + e]);
                }
        }
}

// ---------------- K5: conv3 implicit GEMM (M=512, N=25088, K=4608), 2-term --
// grid (4 m, 196 n). K reordered (rs, c): stage kt -> rs = kt/16, c0=(kt%16)*32
__global__ __launch_bounds__(256, 2) void k_conv_mma() {
    GEMM_VARS();
    int m0 = blockIdx.x * 128, n0 = blockIdx.y * 128;
    const int T = K33 / 32;    // 144 stages
    int gr[2], gb[2], gph[2], gpw[2];
    #pragma unroll
    for (int it = 0; it < 2; it++) {
        int row = it * 64 + (tid >> 2);
        gr[it] = row;
        int col = n0 + row;
        gb[it] = col / HW;
        int p = col - gb[it] * HW;
        gph[it] = p / 14; gpw[it] = p - gph[it] * 14;
    }
    int seg = tid & 3;
    #define ISSUE(kt) {                                                        \
        uint32_t s = sb0 + ((kt) & 1) * STAGE3_B; int k0 = (kt) * 32;          \
        cpa_tile(s,          g_w3_h + (size_t)m0 * K33, K33, k0, tid);         \
        cpa_tile(s + TILE_B, g_w3_l + (size_t)m0 * K33, K33, k0, tid);         \
        int rs = (kt) >> 4, c0 = ((kt) & 15) * 32;                             \
        int dr = rs / 3 - 1, ds = rs - (rs / 3) * 3 - 1;                       \
        _Pragma("unroll")                                                      \
        for (int it = 0; it < 2; it++) {                                       \
            int ih = gph[it] + dr, iw = gpw[it] + ds;                          \
            int ok = ((unsigned)ih < 14u) && ((unsigned)iw < 14u);             \
            size_t pix = (size_t)gb[it] * HW + (ok ? ih * 14 + iw : 0);        \
            size_t gidx = pix * CMID + c0 + seg * 8;                           \
            cp16z(s + 2 * TILE_B + gr[it] * TROW + seg * 16, g_yT_h + gidx, ok); \
        } }
    ISSUE(0); cp_commit();
    for (int kt = 0; kt < T; kt++) {
        if (kt + 1 < T) { ISSUE(kt + 1); cp_commit(); cp_wait<1>(); }
        else cp_wait<0>();
        __syncthreads();
        stage_compute_2A(sb0 + (kt & 1) * STAGE3_B, wm, wn, lane, c);
        __syncthreads();
    }
    #undef ISSUE
    // fused BN + ReLU + GAP
    int b0 = n0 / HW;
    int split = (b0 + 1) * HW - n0;   // local cols < split belong to b0
    #pragma unroll
    for (int am = 0; am < 4; am++)
        #pragma unroll
        for (int half = 0; half < 2; half++) {
            int o = m0 + wm + am * 16 + (lane >> 2) + half * 8;
            float sc = g_scale3[o], sh = g_shift3[o];
            float s0 = 0.f, s1 = 0.f;
            #pragma unroll
            for (int bn = 0; bn < 4; bn++)
                #pragma unroll
                for (int e = 0; e < 2; e++) {
                    float v = fmaxf(c[am][bn][half * 2 + e] * sc + sh, 0.f);
                    int lcol = wn + bn * 8 + 2 * (lane & 3) + e;
                    if (lcol < split) s0 += v; else s1 += v;
                }
            s0 += __shfl_xor_sync(~0u, s0, 1);
            s0 += __shfl_xor_sync(~0u, s0, 2);
            s1 += __shfl_xor_sync(~0u, s1, 1);
            s1 += __shfl_xor_sync(~0u, s1, 2);
            if ((lane & 3) == 0) {
                atomicAdd(&g_zsum[b0 * CMID + o], s0 * (1.f / HW));
                if (split < 128)
                    atomicAdd(&g_zsum[(b0 + 1) * CMID + o], s1 * (1.f / HW));
            }
        }
}

// ---------------- K7: fc1 + ReLU --------------------------------------------
__global__ __launch_bounds__(256) void k_fc1(const float* __restrict__ w,
                                             const float* __restrict__ bias) {
    int gw = (blockIdx.x * blockDim.x + threadIdx.x) >> 5;
    int lane = threadIdx.x & 31;
    if (gw >= BATCH * 200) return;
    int b = gw / 200, j = gw - b * 200;
    const float* zr = g_zsum + b * CMID;
    const float* wr = w + (size_t)j * CMID;
    float s = 0.f;
    for (int k = lane; k < CMID; k += 32) s += zr[k] * wr[k];
    #pragma unroll
    for (int o = 16; o; o >>= 1) s += __shfl_xor_sync(~0u, s, o);
    if (lane == 0) g_h[gw] = fmaxf(s + bias[j], 0.f);
}

// ---------------- K8: fc2 + branch-sum --------------------------------------
__global__ __launch_bounds__(256) void k_fc2(const float* __restrict__ w,
                                             const float* __restrict__ bias,
                                             float* __restrict__ out) {
    int gw = (blockIdx.x * blockDim.x + threadIdx.x) >> 5;
    int lane = threadIdx.x & 31;
    if (gw >= HB * 200) return;
    int b = gw / 200, j = gw - b * 200;
    const float* h1 = g_h + (size_t)b * 200;
    const float* h2 = g_h + (size_t)(b + HB) * 200;
    const float* wr = w + (size_t)j * 200;
    float s = 0.f;
    for (int k = lane; k < 200; k += 32) s += (h1[k] + h2[k]) * wr[k];
    #pragma unroll
    for (int o = 16; o; o >>= 1) s += __shfl_xor_sync(~0u, s, o);
    if (lane == 0) out[gw] = s + 2.f * bias[j];
}

// ---------------- launch ----------------------------------------------------
extern "C" void kernel_launch(void* const* d_in, const int* in_sizes, int n_in,
                              void* d_out, int out_size) {
    const float* f2  = (const float*)d_in[0];
    const float* f3  = (const float*)d_in[1];
    const float* rw  = (const float*)d_in[2];
    const float* rb  = (const float*)d_in[3];
    const float* rg  = (const float*)d_in[4];
    const float* rbe = (const float*)d_in[5];
    const float* rm  = (const float*)d_in[6];
    const float* rv  = (const float*)d_in[7];
    const float* c3w = (const float*)d_in[8];
    const float* c3b = (const float*)d_in[9];
    const float* c3g = (const float*)d_in[10];
    const float* c3be= (const float*)d_in[11];
    const float* c3m = (const float*)d_in[12];
    const float* c3v = (const float*)d_in[13];
    const float* f1w = (const float*)d_in[14];
    const float* f1b = (const float*)d_in[15];
    const float* f2w = (const float*)d_in[16];
    const float* f2b = (const float*)d_in[17];
    float* out = (float*)d_out;

    cudaFuncSetAttribute(k_reduce_mma, cudaFuncAttributeMaxDynamicSharedMemorySize, DYN_SMEM);
    cudaFuncSetAttribute(k_xxt_mma,    cudaFuncAttributeMaxDynamicSharedMemorySize, DYN_SMEM);
    cudaFuncSetAttribute(k_ygemm_mma,  cudaFuncAttributeMaxDynamicSharedMemorySize, DYN3_SMEM);
    cudaFuncSetAttribute(k_conv_mma,   cudaFuncAttributeMaxDynamicSharedMemorySize, DYN3_SMEM);

    k_zero<<<BATCH * CMID / 256, 256>>>();
    prep_bn<<<2, 256>>>(rb, rg, rbe, rm, rv, c3b, c3g, c3be, c3m, c3v);
    cvt_w1<<<(CMID * CIN) / 256, 256>>>(rw);
    cvt_w3<<<(CMID * K33) / 256, 256>>>(c3w);
    cvt_f<<<dim3(7, CIN / 32, BATCH), dim3(32, 8)>>>(f2, f3);

    k_reduce_mma<<<dim3(4, NFLAT / 128), 256, DYN_SMEM>>>();
    k_xxt_mma<<<dim3(4, 4, BATCH), 256, DYN_SMEM>>>();
    k_softmax<<<(BATCH * CMID) / 8, 256>>>();
    k_ygemm_mma<<<dim3(2, 4, BATCH), 256, DYN3_SMEM>>>();
    k_conv_mma<<<dim3(4, NFLAT / 128), 256, DYN3_SMEM>>>();
    k_fc1<<<(BATCH * 200 + 7) / 8, 256>>>(f1w, f1b);
    k_fc2<<<(HB * 200 + 7) / 8, 256>>>(f2w, f2b, out);
}

// round 8
// speedup vs baseline: 4.5653x; 1.0148x over previous
#include <cuda_runtime.h>
#include <cuda_bf16.h>
#include <cstdint>
#include <math_constants.h>

#define EPS 1e-5f
#define HB 64
#define BATCH 128
#define CIN 2048
#define CMID 512
#define HW 196
#define HWP 256
#define KXT 224     // xxt effective K (>=196, /32)
#define K33 4608
#define NFLAT 25088   // 128*196 = 196 tiles of 128 exactly

// ---------------- scratch (static device globals; zero-init at load) --------
__device__ __nv_bfloat16 g_fT_h[(size_t)NFLAT * CIN];
__device__ __nv_bfloat16 g_fT_l[(size_t)NFLAT * CIN];
__device__ __nv_bfloat16 g_x_h [(size_t)BATCH * CMID * HWP];  // pad cols stay 0
__device__ __nv_bfloat16 g_x_l [(size_t)BATCH * CMID * HWP];
__device__ __nv_bfloat16 g_xT_h[(size_t)BATCH * HW * CMID];
__device__ float         g_att [(size_t)BATCH * CMID * CMID];
__device__ __nv_bfloat16 g_att_h[(size_t)BATCH * CMID * CMID];
__device__ __nv_bfloat16 g_yT_h[(size_t)BATCH * HW * CMID];
__device__ __nv_bfloat16 g_w1_h[(size_t)CMID * CIN];
__device__ __nv_bfloat16 g_w1_l[(size_t)CMID * CIN];
__device__ __nv_bfloat16 g_w3_h[(size_t)CMID * K33];   // reordered k = rs*512 + c
__device__ __nv_bfloat16 g_w3_l[(size_t)CMID * K33];
__device__ float g_zsum[BATCH * CMID];
__device__ float g_h[BATCH * 200];
__device__ float g_scale1[CMID], g_shift1[CMID], g_scale3[CMID], g_shift3[CMID];

// ---------------- ptx helpers (all non-'a' gated: sm_80-level) --------------
__device__ __forceinline__ uint32_t smem_u32(const void* p) {
    uint32_t a;
    asm("{ .reg .u64 t; cvta.to.shared.u64 t, %1; cvt.u32.u64 %0, t; }"
        : "=r"(a) : "l"(p));
    return a;
}
__device__ __forceinline__ void cp16(uint32_t dst, const void* src) {
    asm volatile("cp.async.ca.shared.global [%0], [%1], 16;"
                 :: "r"(dst), "l"(src));
}
__device__ __forceinline__ void cp16z(uint32_t dst, const void* src, int ok) {
    int sz = ok ? 16 : 0;
    asm volatile("cp.async.ca.shared.global [%0], [%1], 16, %2;"
                 :: "r"(dst), "l"(src), "r"(sz));
}
__device__ __forceinline__ void cp_commit() {
    asm volatile("cp.async.commit_group;" ::: "memory");
}
template<int N> __device__ __forceinline__ void cp_wait() {
    asm volatile("cp.async.wait_group %0;" :: "n"(N) : "memory");
}
__device__ __forceinline__ void ldm4(uint32_t* r, uint32_t addr) {
    asm volatile("ldmatrix.sync.aligned.m8n8.x4.shared.b16 {%0,%1,%2,%3}, [%4];"
                 : "=r"(r[0]), "=r"(r[1]), "=r"(r[2]), "=r"(r[3]) : "r"(addr));
}
__device__ __forceinline__ void ldm2(uint32_t* r, uint32_t addr) {
    asm volatile("ldmatrix.sync.aligned.m8n8.x2.shared.b16 {%0,%1}, [%2];"
                 : "=r"(r[0]), "=r"(r[1]) : "r"(addr));
}
__device__ __forceinline__ void mma16816(float* c, const uint32_t* a,
                                         const uint32_t* b) {
    asm volatile(
        "mma.sync.aligned.m16n8k16.row.col.f32.bf16.bf16.f32 "
        "{%0,%1,%2,%3}, {%4,%5,%6,%7}, {%8,%9}, {%0,%1,%2,%3};"
        : "+f"(c[0]), "+f"(c[1]), "+f"(c[2]), "+f"(c[3])
        : "r"(a[0]), "r"(a[1]), "r"(a[2]), "r"(a[3]), "r"(b[0]), "r"(b[1]));
}
__device__ __forceinline__ void split_bf16(float v, __nv_bfloat16& hi,
                                           __nv_bfloat16& lo) {
    hi = __float2bfloat16(v);
    lo = __float2bfloat16(v - __bfloat162float(hi));
}

// ---------------- SMEM geometry ---------------------------------------------
#define TROW 80
#define TILE_B (128 * TROW)          // 10240 B
#define STAGE_B (4 * TILE_B)         // Ah, Al, Bh, Bl (reduce/xxt)
#define STAGE3_B (3 * TILE_B)        // Ah, Al, Bh     (conv)
#define STAGE2_B (2 * TILE_B)        // Ah, Bh         (ygemm)
#define DYN_SMEM (2 * STAGE_B)       // 81920 B
#define DYN3_SMEM (3 * STAGE3_B)     // 92160 B (conv, 3-stage)
#define DYN2_SMEM (2 * STAGE2_B)     // 40960 B

// contiguous 128x32 tile load via cp.async: 512 16B chunks / 256 threads
__device__ __forceinline__ void cpa_tile(uint32_t sdst, const __nv_bfloat16* g,
                                         size_t stride, int k0, int tid) {
    #pragma unroll
    for (int it = 0; it < 2; it++) {
        int ch = it * 256 + tid;
        int row = ch >> 2, seg = ch & 3;
        cp16(sdst + row * TROW + seg * 16,
             g + (size_t)row * stride + k0 + seg * 8);
    }
}
__device__ __forceinline__ void cpa_tile_clamp(uint32_t sdst,
                                               const __nv_bfloat16* g,
                                               size_t stride, int row0,
                                               int maxrow, int k0, int tid) {
    #pragma unroll
    for (int it = 0; it < 2; it++) {
        int ch = it * 256 + tid;
        int row = ch >> 2, seg = ch & 3;
        int rg = row0 + row; if (rg > maxrow) rg = maxrow;
        cp16(sdst + row * TROW + seg * 16,
             g + (size_t)rg * stride + k0 + seg * 8);
    }
}

// one k16 slab: 4 m-atoms x 4 n-atoms of m16n8k16
__device__ __forceinline__ void mma_k16(uint32_t aBase, uint32_t bBase, int kk,
                                        int lane, float c[4][4][4]) {
    uint32_t a[4][4], b[4][2];
    int arow = lane & 15, asel = lane >> 4;
    #pragma unroll
    for (int am = 0; am < 4; am++)
        ldm4(a[am], aBase + (am * 16 + arow) * TROW + (kk + asel * 8) * 2);
    int brow = lane & 7, bsel = (lane >> 3) & 1;
    #pragma unroll
    for (int bn = 0; bn < 4; bn++)
        ldm2(b[bn], bBase + (bn * 8 + brow) * TROW + (kk + bsel * 8) * 2);
    #pragma unroll
    for (int am = 0; am < 4; am++)
        #pragma unroll
        for (int bn = 0; bn < 4; bn++)
            mma16816(c[am][bn], a[am], b[bn]);
}

// 2-A variant: (Ahi + Alo) x B, B fragments loaded once
__device__ __forceinline__ void mma_k16_2A(uint32_t aH, uint32_t aL,
                                           uint32_t bBase, int kk, int lane,
                                           float c[4][4][4]) {
    uint32_t a[4][4], b[4][2];
    int arow = lane & 15, asel = lane >> 4;
    int brow = lane & 7, bsel = (lane >> 3) & 1;
    #pragma unroll
    for (int bn = 0; bn < 4; bn++)
        ldm2(b[bn], bBase + (bn * 8 + brow) * TROW + (kk + bsel * 8) * 2);
    #pragma unroll
    for (int am = 0; am < 4; am++)
        ldm4(a[am], aH + (am * 16 + arow) * TROW + (kk + asel * 8) * 2);
    #pragma unroll
    for (int am = 0; am < 4; am++)
        #pragma unroll
        for (int bn = 0; bn < 4; bn++)
            mma16816(c[am][bn], a[am], b[bn]);
    #pragma unroll
    for (int am = 0; am < 4; am++)
        ldm4(a[am], aL + (am * 16 + arow) * TROW + (kk + asel * 8) * 2);
    #pragma unroll
    for (int am = 0; am < 4; am++)
        #pragma unroll
        for (int bn = 0; bn < 4; bn++)
            mma16816(c[am][bn], a[am], b[bn]);
}

// full 3-term stage (reduce/xxt): (Ah,Bh), (Ah,Bl), (Al,Bh)
__device__ __forceinline__ void stage_compute(uint32_t sb, int wm, int wn,
                                              int lane, float c[4][4][4]) {
    uint32_t Ah = sb + wm * TROW,            Al = Ah + TILE_B;
    uint32_t Bh = sb + 2 * TILE_B + wn * TROW, Bl = Bh + TILE_B;
    #pragma unroll
    for (int kk = 0; kk < 32; kk += 16) {
        mma_k16(Ah, Bh, kk, lane, c);
        mma_k16(Ah, Bl, kk, lane, c);
        mma_k16(Al, Bh, kk, lane, c);
    }
}
// 2-term stage (conv): (Ah + Al) x Bh
__device__ __forceinline__ void stage_compute_2A(uint32_t sb, int wm, int wn,
                                                 int lane, float c[4][4][4]) {
    uint32_t Ah = sb + wm * TROW, Al = Ah + TILE_B;
    uint32_t Bh = sb + 2 * TILE_B + wn * TROW;
    #pragma unroll
    for (int kk = 0; kk < 32; kk += 16) mma_k16_2A(Ah, Al, Bh, kk, lane, c);
}
// 1-term stage (ygemm): Ah x Bh
__device__ __forceinline__ void stage_compute_1A(uint32_t sb, int wm, int wn,
                                                 int lane, float c[4][4][4]) {
    uint32_t Ah = sb + wm * TROW;
    uint32_t Bh = sb + TILE_B + wn * TROW;
    #pragma unroll
    for (int kk = 0; kk < 32; kk += 16) mma_k16(Ah, Bh, kk, lane, c);
}

#define GEMM_VARS()                                                            \
    extern __shared__ __align__(16) char dsm[];                                \
    uint32_t sb0 = smem_u32(dsm);                                              \
    int tid = threadIdx.x, wid = tid >> 5, lane = tid & 31;                    \
    int wm = (wid >> 2) * 64, wn = (wid & 3) * 32;                             \
    float c[4][4][4] = {};

// ---------------- small prep kernels ----------------------------------------
__global__ void k_zero() {
    g_zsum[blockIdx.x * blockDim.x + threadIdx.x] = 0.f;
}
__global__ void prep_bn(const float* __restrict__ rb, const float* __restrict__ rg,
                        const float* __restrict__ rbe, const float* __restrict__ rm,
                        const float* __restrict__ rv,
                        const float* __restrict__ cb, const float* __restrict__ cg,
                        const float* __restrict__ cbe, const float* __restrict__ cm,
                        const float* __restrict__ cv) {
    int i = blockIdx.x * blockDim.x + threadIdx.x;
    if (i < CMID) {
        float inv = rg[i] * rsqrtf(rv[i] + EPS);
        g_scale1[i] = inv;
        g_shift1[i] = (rb[i] - rm[i]) * inv + rbe[i];
        float inv3 = cg[i] * rsqrtf(cv[i] + EPS);
        g_scale3[i] = inv3;
        g_shift3[i] = (cb[i] - cm[i]) * inv3 + cbe[i];
    }
}
__global__ void cvt_w1(const float* __restrict__ w) {
    int i = blockIdx.x * blockDim.x + threadIdx.x;
    __nv_bfloat16 hi, lo; split_bf16(w[i], hi, lo);
    g_w1_h[i] = hi; g_w1_l[i] = lo;
}
__global__ void cvt_w3(const float* __restrict__ w) {
    int i = blockIdx.x * blockDim.x + threadIdx.x;   // over 512*4608
    int o = i / K33, k = i - o * K33;
    int rs = k >> 9, cc = k & 511;
    int r = rs / 3, s = rs - r * 3;
    float v = w[((o * CMID + cc) * 3 + r) * 3 + s];
    __nv_bfloat16 hi, lo; split_bf16(v, hi, lo);
    g_w3_h[i] = hi; g_w3_l[i] = lo;
}
// transpose + split features: F[b][c][hw] -> g_fT[b*196+hw][c]
__global__ void cvt_f(const float* __restrict__ f2, const float* __restrict__ f3) {
    __shared__ float t[32][33];
    int hw0 = blockIdx.x * 32, c0 = blockIdx.y * 32, b = blockIdx.z;
    const float* F = (b < HB) ? f2 + (size_t)b * CIN * HW
                              : f3 + (size_t)(b - HB) * CIN * HW;
    int tx = threadIdx.x, ty = threadIdx.y;
    #pragma unroll
    for (int k = 0; k < 4; k++) {
        int cc = c0 + ty + k * 8, hw = hw0 + tx;
        t[ty + k * 8][tx] = (hw < HW) ? F[(size_t)cc * HW + hw] : 0.f;
    }
    __syncthreads();
    #pragma unroll
    for (int k = 0; k < 4; k++) {
        int hw = hw0 + ty + k * 8;
        if (hw < HW) {
            float v = t[tx][ty + k * 8];
            __nv_bfloat16 hi, lo; split_bf16(v, hi, lo);
            size_t idx = ((size_t)b * HW + hw) * CIN + c0 + tx;
            g_fT_h[idx] = hi; g_fT_l[idx] = lo;
        }
    }
}

// ---------------- K1: reduce GEMM (M=512, N=25088, K=2048) + BN/ReLU --------
// grid (4 m, 196 n): m fastest -> 4 consecutive CTAs share each B tile in L2
__global__ __launch_bounds__(256, 2) void k_reduce_mma() {
    GEMM_VARS();
    int m0 = blockIdx.x * 128, n0 = blockIdx.y * 128;
    const int T = CIN / 32;    // 64 stages
    const __nv_bfloat16* Awh = g_w1_h + (size_t)m0 * CIN;
    const __nv_bfloat16* Awl = g_w1_l + (size_t)m0 * CIN;
    const __nv_bfloat16* Bfh = g_fT_h + (size_t)n0 * CIN;
    const __nv_bfloat16* Bfl = g_fT_l + (size_t)n0 * CIN;
    #define ISSUE(kt) {                                                        \
        uint32_t s = sb0 + ((kt) & 1) * STAGE_B; int k0 = (kt) * 32;           \
        cpa_tile(s,              Awh, CIN, k0, tid);                           \
        cpa_tile(s + TILE_B,     Awl, CIN, k0, tid);                           \
        cpa_tile(s + 2 * TILE_B, Bfh, CIN, k0, tid);                           \
        cpa_tile(s + 3 * TILE_B, Bfl, CIN, k0, tid); }
    ISSUE(0); cp_commit();
    for (int kt = 0; kt < T; kt++) {
        if (kt + 1 < T) { ISSUE(kt + 1); cp_commit(); cp_wait<1>(); }
        else cp_wait<0>();
        __syncthreads();
        stage_compute(sb0 + (kt & 1) * STAGE_B, wm, wn, lane, c);
        __syncthreads();
    }
    #undef ISSUE
    #pragma unroll
    for (int am = 0; am < 4; am++) {
        #pragma unroll
        for (int half = 0; half < 2; half++) {
            int o = m0 + wm + am * 16 + (lane >> 2) + half * 8;
            float sc = g_scale1[o], sh = g_shift1[o];
            #pragma unroll
            for (int bn = 0; bn < 4; bn++) {
                #pragma unroll
                for (int e = 0; e < 2; e++) {
                    float v = c[am][bn][half * 2 + e];
                    v = fmaxf(v * sc + sh, 0.f);
                    int col = n0 + wn + bn * 8 + 2 * (lane & 3) + e;
                    int b = col / HW, hw = col - b * HW;
                    __nv_bfloat16 hi, lo; split_bf16(v, hi, lo);
                    size_t i1 = ((size_t)b * CMID + o) * HWP + hw;
                    g_x_h[i1] = hi; g_x_l[i1] = lo;
                    g_xT_h[((size_t)b * HW + hw) * CMID + o] = hi;
                }
            }
        }
    }
}

// ---------------- K2: XXt per batch (M=N=512, K=196 pad 224) ----------------
__global__ __launch_bounds__(256, 2) void k_xxt_mma() {
    GEMM_VARS();
    int n0 = blockIdx.x * 128, m0 = blockIdx.y * 128, b = blockIdx.z;
    const __nv_bfloat16* Xh = g_x_h + (size_t)b * CMID * HWP;
    const __nv_bfloat16* Xl = g_x_l + (size_t)b * CMID * HWP;
    const int T = KXT / 32;    // 7 stages
    #define ISSUE(kt) {                                                        \
        uint32_t s = sb0 + ((kt) & 1) * STAGE_B; int k0 = (kt) * 32;           \
        cpa_tile(s,              Xh + (size_t)m0 * HWP, HWP, k0, tid);         \
        cpa_tile(s + TILE_B,     Xl + (size_t)m0 * HWP, HWP, k0, tid);         \
        cpa_tile(s + 2 * TILE_B, Xh + (size_t)n0 * HWP, HWP, k0, tid);         \
        cpa_tile(s + 3 * TILE_B, Xl + (size_t)n0 * HWP, HWP, k0, tid); }
    ISSUE(0); cp_commit();
    for (int kt = 0; kt < T; kt++) {
        if (kt + 1 < T) { ISSUE(kt + 1); cp_commit(); cp_wait<1>(); }
        else cp_wait<0>();
        __syncthreads();
        stage_compute(sb0 + (kt & 1) * STAGE_B, wm, wn, lane, c);
        __syncthreads();
    }
    #undef ISSUE
    float* out = g_att + (size_t)b * CMID * CMID;
    #pragma unroll
    for (int am = 0; am < 4; am++)
        #pragma unroll
        for (int half = 0; half < 2; half++) {
            int r = m0 + wm + am * 16 + (lane >> 2) + half * 8;
            #pragma unroll
            for (int bn = 0; bn < 4; bn++) {
                int col = n0 + wn + bn * 8 + 2 * (lane & 3);
                out[(size_t)r * CMID + col]     = c[am][bn][half * 2 + 0];
                out[(size_t)r * CMID + col + 1] = c[am][bn][half * 2 + 1];
            }
        }
}

// ---------------- K3: softmax(-S) rowwise -> bf16 (single) ------------------
__global__ __launch_bounds__(256) void k_softmax() {
    int gw = (blockIdx.x * blockDim.x + threadIdx.x) >> 5;
    int lane = threadIdx.x & 31;
    if (gw >= BATCH * CMID) return;
    const float* row = g_att + (size_t)gw * CMID;
    float mn = CUDART_INF_F;
    #pragma unroll
    for (int t = 0; t < 16; t++) mn = fminf(mn, row[lane + t * 32]);
    #pragma unroll
    for (int o = 16; o; o >>= 1) mn = fminf(mn, __shfl_xor_sync(~0u, mn, o));
    float e[16], sum = 0.f;
    #pragma unroll
    for (int t = 0; t < 16; t++) { e[t] = __expf(mn - row[lane + t * 32]); sum += e[t]; }
    #pragma unroll
    for (int o = 16; o; o >>= 1) sum += __shfl_xor_sync(~0u, sum, o);
    float inv = 1.f / sum;
    #pragma unroll
    for (int t = 0; t < 16; t++)
        g_att_h[(size_t)gw * CMID + lane + t * 32] = __float2bfloat16(e[t] * inv);
}

// ---------------- K4: y = att @ X (M=512, N=196pad256, K=512), 1-term -------
__global__ __launch_bounds__(256, 2) void k_ygemm_mma() {
    GEMM_VARS();
    int n0 = blockIdx.x * 128, m0 = blockIdx.y * 128, b = blockIdx.z;
    const __nv_bfloat16* Ah = g_att_h + ((size_t)b * CMID + m0) * CMID;
    const __nv_bfloat16* Bh = g_xT_h + (size_t)b * HW * CMID;
    const int T = CMID / 32;   // 16 stages
    #define ISSUE(kt) {                                                        \
        uint32_t s = sb0 + ((kt) & 1) * STAGE2_B; int k0 = (kt) * 32;          \
        cpa_tile(s, Ah, CMID, k0, tid);                                        \
        cpa_tile_clamp(s + TILE_B, Bh, CMID, n0, HW - 1, k0, tid); }
    ISSUE(0); cp_commit();
    for (int kt = 0; kt < T; kt++) {
        if (kt + 1 < T) { ISSUE(kt + 1); cp_commit(); cp_wait<1>(); }
        else cp_wait<0>();
        __syncthreads();
        stage_compute_1A(sb0 + (kt & 1) * STAGE2_B, wm, wn, lane, c);
        __syncthreads();
    }
    #undef ISSUE
    #pragma unroll
    for (int am = 0; am < 4; am++)
        #pragma unroll
        for (int half = 0; half < 2; half++) {
            int i = m0 + wm + am * 16 + (lane >> 2) + half * 8;
            #pragma unroll
            for (int bn = 0; bn < 4; bn++)
                #pragma unroll
                for (int e = 0; e < 2; e++) {
                    int col = n0 + wn + bn * 8 + 2 * (lane & 3) + e;
                    if (col < HW)
                        g_yT_h[((size_t)b * HW + col) * CMID + i] =
                            __float2bfloat16(c[am][bn][half * 2 + e]);
                }
        }
}

// ---------------- K5: conv3 implicit GEMM (M=512, N=25088, K=4608), 2-term --
// grid (4 m, 196 n). 3-stage pipeline. K reordered (rs, c).
__global__ __launch_bounds__(256, 2) void k_conv_mma() {
    GEMM_VARS();
    int m0 = blockIdx.x * 128, n0 = blockIdx.y * 128;
    const int T = K33 / 32;    // 144 stages
    int gr[2], gb[2], gph[2], gpw[2];
    #pragma unroll
    for (int it = 0; it < 2; it++) {
        int row = it * 64 + (tid >> 2);
        gr[it] = row;
        int col = n0 + row;
        gb[it] = col / HW;
        int p = col - gb[it] * HW;
        gph[it] = p / 14; gpw[it] = p - gph[it] * 14;
    }
    int seg = tid & 3;
    #define ISSUE(kt) {                                                        \
        uint32_t s = sb0 + ((kt) % 3) * STAGE3_B; int k0 = (kt) * 32;          \
        cpa_tile(s,          g_w3_h + (size_t)m0 * K33, K33, k0, tid);         \
        cpa_tile(s + TILE_B, g_w3_l + (size_t)m0 * K33, K33, k0, tid);         \
        int rs = (kt) >> 4, c0 = ((kt) & 15) * 32;                             \
        int dr = rs / 3 - 1, ds = rs - (rs / 3) * 3 - 1;                       \
        _Pragma("unroll")                                                      \
        for (int it = 0; it < 2; it++) {                                       \
            int ih = gph[it] + dr, iw = gpw[it] + ds;                          \
            int ok = ((unsigned)ih < 14u) && ((unsigned)iw < 14u);             \
            size_t pix = (size_t)gb[it] * HW + (ok ? ih * 14 + iw : 0);        \
            size_t gidx = pix * CMID + c0 + seg * 8;                           \
            cp16z(s + 2 * TILE_B + gr[it] * TROW + seg * 16, g_yT_h + gidx, ok); \
        } }
    ISSUE(0); cp_commit();
    ISSUE(1); cp_commit();
    for (int kt = 0; kt < T; kt++) {
        if (kt + 2 < T) { ISSUE(kt + 2); cp_commit(); cp_wait<2>(); }
        else if (kt + 1 < T) cp_wait<1>();
        else cp_wait<0>();
        __syncthreads();
        stage_compute_2A(sb0 + (kt % 3) * STAGE3_B, wm, wn, lane, c);
        __syncthreads();
    }
    #undef ISSUE
    // fused BN + ReLU + GAP
    int b0 = n0 / HW;
    int split = (b0 + 1) * HW - n0;   // local cols < split belong to b0
    #pragma unroll
    for (int am = 0; am < 4; am++)
        #pragma unroll
        for (int half = 0; half < 2; half++) {
            int o = m0 + wm + am * 16 + (lane >> 2) + half * 8;
            float sc = g_scale3[o], sh = g_shift3[o];
            float s0 = 0.f, s1 = 0.f;
            #pragma unroll
            for (int bn = 0; bn < 4; bn++)
                #pragma unroll
                for (int e = 0; e < 2; e++) {
                    float v = fmaxf(c[am][bn][half * 2 + e] * sc + sh, 0.f);
                    int lcol = wn + bn * 8 + 2 * (lane & 3) + e;
                    if (lcol < split) s0 += v; else s1 += v;
                }
            s0 += __shfl_xor_sync(~0u, s0, 1);
            s0 += __shfl_xor_sync(~0u, s0, 2);
            s1 += __shfl_xor_sync(~0u, s1, 1);
            s1 += __shfl_xor_sync(~0u, s1, 2);
            if ((lane & 3) == 0) {
                atomicAdd(&g_zsum[b0 * CMID + o], s0 * (1.f / HW));
                if (split < 128)
                    atomicAdd(&g_zsum[(b0 + 1) * CMID + o], s1 * (1.f / HW));
            }
        }
}

// ---------------- K7: fc1 + ReLU --------------------------------------------
__global__ __launch_bounds__(256) void k_fc1(const float* __restrict__ w,
                                             const float* __restrict__ bias) {
    int gw = (blockIdx.x * blockDim.x + threadIdx.x) >> 5;
    int lane = threadIdx.x & 31;
    if (gw >= BATCH * 200) return;
    int b = gw / 200, j = gw - b * 200;
    const float* zr = g_zsum + b * CMID;
    const float* wr = w + (size_t)j * CMID;
    float s = 0.f;
    for (int k = lane; k < CMID; k += 32) s += zr[k] * wr[k];
    #pragma unroll
    for (int o = 16; o; o >>= 1) s += __shfl_xor_sync(~0u, s, o);
    if (lane == 0) g_h[gw] = fmaxf(s + bias[j], 0.f);
}

// ---------------- K8: fc2 + branch-sum --------------------------------------
__global__ __launch_bounds__(256) void k_fc2(const float* __restrict__ w,
                                             const float* __restrict__ bias,
                                             float* __restrict__ out) {
    int gw = (blockIdx.x * blockDim.x + threadIdx.x) >> 5;
    int lane = threadIdx.x & 31;
    if (gw >= HB * 200) return;
    int b = gw / 200, j = gw - b * 200;
    const float* h1 = g_h + (size_t)b * 200;
    const float* h2 = g_h + (size_t)(b + HB) * 200;
    const float* wr = w + (size_t)j * 200;
    float s = 0.f;
    for (int k = lane; k < 200; k += 32) s += (h1[k] + h2[k]) * wr[k];
    #pragma unroll
    for (int o = 16; o; o >>= 1) s += __shfl_xor_sync(~0u, s, o);
    if (lane == 0) out[gw] = s + 2.f * bias[j];
}

// ---------------- launch ----------------------------------------------------
extern "C" void kernel_launch(void* const* d_in, const int* in_sizes, int n_in,
                              void* d_out, int out_size) {
    const float* f2  = (const float*)d_in[0];
    const float* f3  = (const float*)d_in[1];
    const float* rw  = (const float*)d_in[2];
    const float* rb  = (const float*)d_in[3];
    const float* rg  = (const float*)d_in[4];
    const float* rbe = (const float*)d_in[5];
    const float* rm  = (const float*)d_in[6];
    const float* rv  = (const float*)d_in[7];
    const float* c3w = (const float*)d_in[8];
    const float* c3b = (const float*)d_in[9];
    const float* c3g = (const float*)d_in[10];
    const float* c3be= (const float*)d_in[11];
    const float* c3m = (const float*)d_in[12];
    const float* c3v = (const float*)d_in[13];
    const float* f1w = (const float*)d_in[14];
    const float* f1b = (const float*)d_in[15];
    const float* f2w = (const float*)d_in[16];
    const float* f2b = (const float*)d_in[17];
    float* out = (float*)d_out;

    cudaFuncSetAttribute(k_reduce_mma, cudaFuncAttributeMaxDynamicSharedMemorySize, DYN_SMEM);
    cudaFuncSetAttribute(k_xxt_mma,    cudaFuncAttributeMaxDynamicSharedMemorySize, DYN_SMEM);
    cudaFuncSetAttribute(k_ygemm_mma,  cudaFuncAttributeMaxDynamicSharedMemorySize, DYN2_SMEM);
    cudaFuncSetAttribute(k_conv_mma,   cudaFuncAttributeMaxDynamicSharedMemorySize, DYN3_SMEM);

    k_zero<<<BATCH * CMID / 256, 256>>>();
    prep_bn<<<2, 256>>>(rb, rg, rbe, rm, rv, c3b, c3g, c3be, c3m, c3v);
    cvt_w1<<<(CMID * CIN) / 256, 256>>>(rw);
    cvt_w3<<<(CMID * K33) / 256, 256>>>(c3w);
    cvt_f<<<dim3(7, CIN / 32, BATCH), dim3(32, 8)>>>(f2, f3);

    k_reduce_mma<<<dim3(4, NFLAT / 128), 256, DYN_SMEM>>>();
    k_xxt_mma<<<dim3(4, 4, BATCH), 256, DYN_SMEM>>>();
    k_softmax<<<(BATCH * CMID) / 8, 256>>>();
    k_ygemm_mma<<<dim3(2, 4, BATCH), 256, DYN2_SMEM>>>();
    k_conv_mma<<<dim3(4, NFLAT / 128), 256, DYN3_SMEM>>>();
    k_fc1<<<(BATCH * 200 + 7) / 8, 256>>>(f1w, f1b);
    k_fc2<<<(HB * 200 + 7) / 8, 256>>>(f2w, f2b, out);
}